// round 15
// baseline (speedup 1.0000x reference)
#include <cuda_runtime.h>
#include <math.h>
#include <stdint.h>

#define Nn 4096
#define Ee 131072
#define FIN 512
#define Hh 64
#define Cc 16
#define Qq 6

// ---------------- scratch (static device memory; no allocations) ----------------
__device__ float g_s1d[Nn * Nn];
__device__ float g_s2d[Nn * Nn];
__device__ float g_aa1[Nn * Nn];
__device__ float g_aa2[Nn * Nn];
__device__ float g_h1[Nn * Hh];
__device__ float g_x1[Nn * Hh];
__device__ float g_hc[Nn * Cc];
__device__ float g_xout[Nn * Cc];
__device__ float g_deg[Nn];
__device__ float g_Y[2 * Nn * Qq];
__device__ float g_Z[2 * Nn * Qq];
__device__ float g_Bt[2 * Nn * Qq];
__device__ float g_V[2 * Nn * Qq];
__device__ float g_w[2 * 3 * Nn];
__device__ float g_t[2 * 3 * Nn];
__device__ float g_sg1[Ee];
__device__ float g_sg2[Ee];
__device__ float g_red[16];     // 0 sum_s1, 1 sumsq_s1, 2 sum_s2, 3 sumsq_s2, 5 calib
__device__ double g_dred[16];   // per run r: [8r+2]=nuc, [8r+3]=inv_ww
__device__ double g_dredp[2 * 32];  // per-run dot partials (16 blocks x 2)

// ---------------- utility ----------------
__global__ void fill_kernel(float* __restrict__ p, float v, int n) {
    int idx = blockIdx.x * blockDim.x + threadIdx.x;
    if (idx < n) p[idx] = v;
}

__global__ void fill4_kernel(float4* __restrict__ p, float v, int n4) {
    int idx = blockIdx.x * blockDim.x + threadIdx.x;
    if (idx < n4) p[idx] = make_float4(v, v, v, v);
}

__global__ void zero_red_kernel(float* red, double* dred) {
    if (threadIdx.x < 16) red[threadIdx.x] = 0.f;
    if (threadIdx.x < 16) dred[threadIdx.x] = 0.0;
}

__global__ void copy2_kernel(const float* __restrict__ a, float* __restrict__ oa,
                             const float* __restrict__ b, float* __restrict__ ob) {
    int i = blockIdx.x * blockDim.x + threadIdx.x;
    if (i < Ee) { oa[i] = a[i]; ob[i] = b[i]; }
}

// ---------------- edge gate 1: 512 -> 64 -> 1 MLP, 4 edges per thread ----------------
__global__ void gate1_kernel(const float* __restrict__ x, const int* __restrict__ ei,
                             const float* __restrict__ w1, const float* __restrict__ b1,
                             const float* __restrict__ w2, const float* __restrict__ b2,
                             float* __restrict__ sout) {
    __shared__ float sred[8][4];
    int tid = threadIdx.x;
    int j = tid & 63;
    int g = tid >> 6;                 // 0..3, 4 edges each -> 16 edges per block
    int e0 = blockIdx.x * 16 + g * 4;
    const float* xs0 = x + (size_t)ei[e0 + 0] * FIN;
    const float* xs1 = x + (size_t)ei[e0 + 1] * FIN;
    const float* xs2 = x + (size_t)ei[e0 + 2] * FIN;
    const float* xs3 = x + (size_t)ei[e0 + 3] * FIN;
    const float* xd0 = x + (size_t)ei[Ee + e0 + 0] * FIN;
    const float* xd1 = x + (size_t)ei[Ee + e0 + 1] * FIN;
    const float* xd2 = x + (size_t)ei[Ee + e0 + 2] * FIN;
    const float* xd3 = x + (size_t)ei[Ee + e0 + 3] * FIN;
    float bb = b1[j];
    float a0 = bb, a1 = bb, a2 = bb, a3 = bb;
#pragma unroll 4
    for (int f = 0; f < FIN; f++) {
        float w = w1[f * Hh + j];
        a0 += (xs0[f] - xd0[f]) * w;
        a1 += (xs1[f] - xd1[f]) * w;
        a2 += (xs2[f] - xd2[f]) * w;
        a3 += (xs3[f] - xd3[f]) * w;
    }
    float w2j = w2[j];
    float p0 = fmaxf(a0, 0.f) * w2j;
    float p1 = fmaxf(a1, 0.f) * w2j;
    float p2 = fmaxf(a2, 0.f) * w2j;
    float p3 = fmaxf(a3, 0.f) * w2j;
    for (int o = 16; o; o >>= 1) {
        p0 += __shfl_down_sync(0xffffffffu, p0, o);
        p1 += __shfl_down_sync(0xffffffffu, p1, o);
        p2 += __shfl_down_sync(0xffffffffu, p2, o);
        p3 += __shfl_down_sync(0xffffffffu, p3, o);
    }
    int wrp = tid >> 5;
    if ((tid & 31) == 0) { sred[wrp][0] = p0; sred[wrp][1] = p1; sred[wrp][2] = p2; sred[wrp][3] = p3; }
    __syncthreads();
    if (tid < 16) {
        int gg = tid >> 2, r = tid & 3;
        float agg = sred[2 * gg][r] + sred[2 * gg + 1][r] + b2[0];
        agg *= agg;
        float s = 1.f / (1.f + expf(-agg));
        sout[blockIdx.x * 16 + gg * 4 + r] = fminf(fmaxf(s, 0.f), 1.f);
    }
}

// ---------------- edge gate 2: 64 -> 32 -> 1 (warp per edge) ----------------
__global__ void gate2_kernel(const float* __restrict__ x1, const int* __restrict__ ei,
                             const float* __restrict__ w1, const float* __restrict__ b1,
                             const float* __restrict__ w2, const float* __restrict__ b2,
                             float* __restrict__ sout) {
    int wrp = threadIdx.x >> 5, lane = threadIdx.x & 31;
    int e = blockIdx.x * 8 + wrp;
    const float* xs = x1 + (size_t)ei[e] * Hh;
    const float* xd = x1 + (size_t)ei[Ee + e] * Hh;
    float acc = b1[lane];
#pragma unroll
    for (int f = 0; f < Hh; f++)
        acc += (xs[f] - xd[f]) * w1[f * 32 + lane];
    float p = fmaxf(acc, 0.f) * w2[lane];
    for (int o = 16; o; o >>= 1) p += __shfl_down_sync(0xffffffffu, p, o);
    if (lane == 0) {
        float agg = p + b2[0];
        agg *= agg;
        float s = 1.f / (1.f + expf(-agg));
        sout[e] = fminf(fmaxf(s, 0.f), 1.f);
    }
}

// ---------------- dense x @ W ----------------
template <int FI, int FO>
__global__ void xw_kernel(const float* __restrict__ x, const float* __restrict__ W,
                          float* __restrict__ out) {
    int idx = blockIdx.x * blockDim.x + threadIdx.x;
    if (idx >= Nn * FO) return;
    int n = idx / FO, j = idx % FO;
    const float* xr = x + (size_t)n * FI;
    float acc = 0.f;
#pragma unroll 8
    for (int f = 0; f < FI; f++)
        acc += xr[f] * W[f * FO + j];
    out[idx] = acc;
}

// ---------------- GCN aggregation helpers ----------------
__global__ void deg_acc_kernel(const int* __restrict__ ei, const float* __restrict__ s,
                               float* __restrict__ deg) {
    int e = blockIdx.x * blockDim.x + threadIdx.x;
    if (e < Ee) atomicAdd(&deg[ei[Ee + e]], s[e]);
}

__global__ void deg_rsqrt_kernel(float* __restrict__ deg) {
    int i = blockIdx.x * blockDim.x + threadIdx.x;
    if (i < Nn) deg[i] = rsqrtf(deg[i]);   // deg >= 1 (self loop)
}

template <int F>
__global__ void init_out_kernel(const float* __restrict__ h, const float* __restrict__ dis,
                                float* __restrict__ out) {
    int idx = blockIdx.x * blockDim.x + threadIdx.x;
    if (idx >= Nn * F) return;
    int n = idx / F;
    float d = dis[n];
    out[idx] = d * d * h[idx];
}

template <int F>
__global__ void scatter_kernel(const int* __restrict__ ei, const float* __restrict__ s,
                               const float* __restrict__ dis, const float* __restrict__ h,
                               float* __restrict__ out) {
    int idx = blockIdx.x * blockDim.x + threadIdx.x;
    if (idx >= Ee * F) return;
    int e = idx / F, f = idx % F;
    int si = ei[e], di = ei[Ee + e];
    float nrm = dis[si] * s[e] * dis[di];
    atomicAdd(&out[(size_t)di * F + f], nrm * h[(size_t)si * F + f]);
}

template <int F, int RELU>
__global__ void bias_act_kernel(float* __restrict__ p, const float* __restrict__ b) {
    int idx = blockIdx.x * blockDim.x + threadIdx.x;
    if (idx >= Nn * F) return;
    float v = p[idx] + b[idx % F];
    p[idx] = RELU ? fmaxf(v, 0.f) : v;
}

// ---------------- softmax + top2 ----------------
__global__ void softmax_kernel(const float* __restrict__ xo, float* __restrict__ olog,
                               float* __restrict__ osm, float* __restrict__ red) {
    int n = blockIdx.x * blockDim.x + threadIdx.x;
    if (n >= Nn) return;
    float v[Cc];
    float m1 = -1e30f, m2 = -1e30f;
#pragma unroll
    for (int c = 0; c < Cc; c++) {
        float a = xo[n * Cc + c];
        v[c] = a;
        if (a > m1) { m2 = m1; m1 = a; }
        else if (a > m2) m2 = a;
    }
    float se = 0.f;
#pragma unroll
    for (int c = 0; c < Cc; c++) se += expf(v[c] - m1);
    float lse = logf(se);
#pragma unroll
    for (int c = 0; c < Cc; c++) {
        olog[n * Cc + c] = v[c] - m1 - lse;
        osm[n * Cc + c] = expf(v[c] - m1) / se;
    }
    atomicAdd(&red[5], m2 - m1);   // calib = -top1 + top2
}

// ---------------- consist reductions ----------------
__global__ void consist_kernel(const float* __restrict__ s1, const float* __restrict__ s2,
                               float* __restrict__ red) {
    __shared__ float sm[256];
    int tid = threadIdx.x;
    int idx = blockIdx.x * 256 + tid;
    float a = s1[idx], b = s2[idx];
    float vals[4] = {a, a * a, b, b * b};
#pragma unroll
    for (int v = 0; v < 4; v++) {
        sm[tid] = vals[v];
        __syncthreads();
        for (int o = 128; o; o >>= 1) { if (tid < o) sm[tid] += sm[tid + o]; __syncthreads(); }
        if (tid == 0) atomicAdd(&red[v], sm[0]);
        __syncthreads();
    }
}

// ---------------- dense adjacency scatter ----------------
__global__ void scatter_dense_kernel(const int* __restrict__ ei, const float* __restrict__ s,
                                     float* __restrict__ sd) {
    int e = blockIdx.x * blockDim.x + threadIdx.x;
    if (e < Ee) atomicAdd(&sd[(size_t)ei[e] * Nn + ei[Ee + e]], s[e]);
}

// ---------------- tf32 helpers ----------------
__device__ __forceinline__ uint32_t f2tf32(float x) {
    uint32_t u;
    asm("cvt.rna.tf32.f32 %0, %1;" : "=r"(u) : "f"(x));
    return u;
}

__device__ __forceinline__ void mma_tf32(float* c, const uint32_t* a, const uint32_t* b) {
    asm volatile(
        "mma.sync.aligned.m16n8k8.row.col.f32.tf32.tf32.f32 "
        "{%0,%1,%2,%3},{%4,%5,%6,%7},{%8,%9},{%0,%1,%2,%3};"
        : "+f"(c[0]), "+f"(c[1]), "+f"(c[2]), "+f"(c[3])
        : "r"(a[0]), "r"(a[1]), "r"(a[2]), "r"(a[3]), "r"(b[0]), "r"(b[1]));
}

// ---------------- SYRK (tensor cores, tf32): C = A A^T, lower-tri tiles + mirror ----------
__global__ void __launch_bounds__(256, 2)
syrk_tc_kernel(const float* __restrict__ A, float* __restrict__ C) {
    int t = blockIdx.x;
    int bi = 0;
    while ((bi + 1) * (bi + 2) / 2 <= t) bi++;
    int bj = t - bi * (bi + 1) / 2;          // bi >= bj
    int I = bi * 128, J = bj * 128;

    __shared__ uint32_t As[128][32];
    __shared__ uint32_t Bs[128][32];

    int tid = threadIdx.x;
    int wid = tid >> 5, lane = tid & 31;
    int warp_m = wid >> 1;
    int warp_n = wid & 1;
    int lr = lane >> 2;
    int lk = lane & 3;

    float acc[2][8][4];
#pragma unroll
    for (int tm = 0; tm < 2; tm++)
#pragma unroll
        for (int tn = 0; tn < 8; tn++)
#pragma unroll
            for (int i = 0; i < 4; i++) acc[tm][tn][i] = 0.f;

    for (int k0 = 0; k0 < Nn; k0 += 32) {
#pragma unroll
        for (int i = 0; i < 4; i++) {
            int li = tid + i * 256;
            int row = li >> 3;
            int kq = (li & 7) << 2;
            float4 va = *(const float4*)(A + (size_t)(I + row) * Nn + k0 + kq);
            float4 vb = *(const float4*)(A + (size_t)(J + row) * Nn + k0 + kq);
            int pc = (kq + ((row & 7) << 2)) & 31;
            As[row][pc + 0] = f2tf32(va.x); As[row][pc + 1] = f2tf32(va.y);
            As[row][pc + 2] = f2tf32(va.z); As[row][pc + 3] = f2tf32(va.w);
            Bs[row][pc + 0] = f2tf32(vb.x); Bs[row][pc + 1] = f2tf32(vb.y);
            Bs[row][pc + 2] = f2tf32(vb.z); Bs[row][pc + 3] = f2tf32(vb.w);
        }
        __syncthreads();
#pragma unroll
        for (int kk = 0; kk < 32; kk += 8) {
            uint32_t af[2][4];
#pragma unroll
            for (int tm = 0; tm < 2; tm++) {
                int r = warp_m * 32 + tm * 16 + lr;
                int sw = (lr << 2);
                int c1 = (kk + lk + sw) & 31;
                int c2 = (kk + lk + 4 + sw) & 31;
                af[tm][0] = As[r][c1];
                af[tm][1] = As[r + 8][c1];
                af[tm][2] = As[r][c2];
                af[tm][3] = As[r + 8][c2];
            }
            uint32_t bf[8][2];
#pragma unroll
            for (int tn = 0; tn < 8; tn++) {
                int c = warp_n * 64 + tn * 8 + lr;
                int sw = (lr << 2);
                bf[tn][0] = Bs[c][(kk + lk + sw) & 31];
                bf[tn][1] = Bs[c][(kk + lk + 4 + sw) & 31];
            }
#pragma unroll
            for (int tm = 0; tm < 2; tm++)
#pragma unroll
                for (int tn = 0; tn < 8; tn++)
                    mma_tf32(acc[tm][tn], af[tm], bf[tn]);
        }
        __syncthreads();
    }

#pragma unroll
    for (int tm = 0; tm < 2; tm++) {
#pragma unroll
        for (int tn = 0; tn < 8; tn++) {
            int r = I + warp_m * 32 + tm * 16 + lr;
            int c = J + warp_n * 64 + tn * 8 + (lk << 1);
            C[(size_t)r * Nn + c] = acc[tm][tn][0];
            C[(size_t)r * Nn + c + 1] = acc[tm][tn][1];
            C[(size_t)(r + 8) * Nn + c] = acc[tm][tn][2];
            C[(size_t)(r + 8) * Nn + c + 1] = acc[tm][tn][3];
            if (bi != bj) {
                C[(size_t)c * Nn + r] = acc[tm][tn][0];
                C[(size_t)(c + 1) * Nn + r] = acc[tm][tn][1];
                C[(size_t)c * Nn + r + 8] = acc[tm][tn][2];
                C[(size_t)(c + 1) * Nn + r + 8] = acc[tm][tn][3];
            }
        }
    }
}

// ---------------- Y = A @ X  (X is [N,6]) ----------------
__global__ void matA_X_kernel(const float* __restrict__ A, const float* __restrict__ X,
                              float* __restrict__ Y) {
    __shared__ float sm[128 * Qq];
    int n = blockIdx.x;
    int tid = threadIdx.x;
    float acc[Qq] = {0, 0, 0, 0, 0, 0};
    const float* row = A + (size_t)n * Nn;
    for (int k = tid; k < Nn; k += 128) {
        float a = row[k];
#pragma unroll
        for (int q = 0; q < Qq; q++) acc[q] += a * X[k * Qq + q];
    }
#pragma unroll
    for (int q = 0; q < Qq; q++) sm[tid * Qq + q] = acc[q];
    __syncthreads();
    for (int o = 64; o; o >>= 1) {
        if (tid < o)
#pragma unroll
            for (int q = 0; q < Qq; q++) sm[tid * Qq + q] += sm[(tid + o) * Qq + q];
        __syncthreads();
    }
    if (tid < Qq) Y[n * Qq + tid] = sm[tid];
}

// ---------------- Z += A^T @ X (grid.y splits k, atomic accumulate; Z prezeroed) ----------------
__global__ void matAT_X_kernel(const float* __restrict__ A, const float* __restrict__ X,
                               float* __restrict__ Z) {
    __shared__ float Xs[512 * Qq];
    int n = blockIdx.x * 128 + threadIdx.x;
    int k0 = blockIdx.y * 512;
    for (int i = threadIdx.x; i < 512 * Qq; i += 128) Xs[i] = X[k0 * Qq + i];
    __syncthreads();
    float acc[Qq] = {0, 0, 0, 0, 0, 0};
    for (int kk = 0; kk < 512; kk++) {
        float a = A[(size_t)(k0 + kk) * Nn + n];
#pragma unroll
        for (int q = 0; q < Qq; q++) acc[q] += a * Xs[kk * Qq + q];
    }
#pragma unroll
    for (int q = 0; q < Qq; q++) atomicAdd(&Z[n * Qq + q], acc[q]);
}

// ---------------- single-block MGS QR on [N,6], 1024 thr, fp64, fused dots ----------------
__global__ void qr6f_kernel(float* __restrict__ Y) {
    __shared__ double red5[1024 * 5];
    __shared__ double coefs[8];
    int tid = threadIdx.x;
    for (int j = 0; j < Qq; j++) {
        double p = 0.0;
        for (int n = tid; n < Nn; n += 1024) { double v = Y[n * Qq + j]; p += v * v; }
        red5[tid] = p; __syncthreads();
        for (int o = 512; o; o >>= 1) { if (tid < o) red5[tid] += red5[tid + o]; __syncthreads(); }
        if (tid == 0) coefs[0] = (red5[0] > 0.0) ? (1.0 / sqrt(red5[0])) : 0.0;
        __syncthreads();
        float inv = (float)coefs[0];
        for (int n = tid; n < Nn; n += 1024) Y[n * Qq + j] *= inv;
        __syncthreads();
        int nl = Qq - 1 - j;
        if (nl > 0) {
            double d[5] = {0, 0, 0, 0, 0};
            for (int n = tid; n < Nn; n += 1024) {
                double yj = Y[n * Qq + j];
                for (int l = 0; l < nl; l++) d[l] += yj * (double)Y[n * Qq + j + 1 + l];
            }
            for (int l = 0; l < nl; l++) red5[tid * 5 + l] = d[l];
            __syncthreads();
            for (int o = 512; o; o >>= 1) {
                if (tid < o)
                    for (int l = 0; l < nl; l++) red5[tid * 5 + l] += red5[(tid + o) * 5 + l];
                __syncthreads();
            }
            if (tid == 0)
                for (int l = 0; l < nl; l++) coefs[l] = red5[l];
            __syncthreads();
            for (int n = tid; n < Nn; n += 1024) {
                float yj = Y[n * Qq + j];
                for (int l = 0; l < nl; l++)
                    Y[n * Qq + j + 1 + l] -= (float)coefs[l] * yj;
            }
            __syncthreads();
        }
    }
}

// ---------------- one-sided Jacobi SVD on M=[N,6], 1024 thr: V = normalized cols, desc ----
__global__ void osj_kernel(float* __restrict__ M, float* __restrict__ V) {
    __shared__ double sa[1024], sb[1024], sg[1024];
    __shared__ double rot[3];
    __shared__ double nrm[Qq];
    __shared__ int nrot;
    int tid = threadIdx.x;
    for (int sweep = 0; sweep < 10; sweep++) {
        if (tid == 0) nrot = 0;
        __syncthreads();
        for (int p = 0; p < Qq - 1; p++) {
            for (int q = p + 1; q < Qq; q++) {
                double da = 0.0, db = 0.0, dg = 0.0;
                for (int n = tid; n < Nn; n += 1024) {
                    double mp = M[n * Qq + p], mq = M[n * Qq + q];
                    da += mp * mp; db += mq * mq; dg += mp * mq;
                }
                sa[tid] = da; sb[tid] = db; sg[tid] = dg; __syncthreads();
                for (int o = 512; o; o >>= 1) {
                    if (tid < o) { sa[tid] += sa[tid + o]; sb[tid] += sb[tid + o]; sg[tid] += sg[tid + o]; }
                    __syncthreads();
                }
                if (tid == 0) {
                    double a = sa[0], b = sb[0], g = sg[0];
                    double thr = 1e-15 * sqrt(fmax(a * b, 0.0));
                    if (fabs(g) > thr && fabs(g) > 0.0) {
                        double z = (b - a) / (2.0 * g);
                        double tt = ((z >= 0.0) ? 1.0 : -1.0) / (fabs(z) + sqrt(1.0 + z * z));
                        double c = 1.0 / sqrt(1.0 + tt * tt);
                        rot[0] = c; rot[1] = tt * c; rot[2] = 1.0;
                        nrot++;
                    } else rot[2] = 0.0;
                }
                __syncthreads();
                if (rot[2] != 0.0) {
                    float c = (float)rot[0], s = (float)rot[1];
                    for (int n = tid; n < Nn; n += 1024) {
                        float mp = M[n * Qq + p], mq = M[n * Qq + q];
                        M[n * Qq + p] = c * mp - s * mq;
                        M[n * Qq + q] = s * mp + c * mq;
                    }
                }
                __syncthreads();
            }
        }
        if (nrot == 0) break;
        __syncthreads();
    }
    for (int j = 0; j < Qq; j++) {
        double d = 0.0;
        for (int n = tid; n < Nn; n += 1024) { double m = M[n * Qq + j]; d += m * m; }
        sa[tid] = d; __syncthreads();
        for (int o = 512; o; o >>= 1) { if (tid < o) sa[tid] += sa[tid + o]; __syncthreads(); }
        if (tid == 0) nrm[j] = sqrt(sa[0]);
        __syncthreads();
    }
    int idx[Qq] = {0, 1, 2, 3, 4, 5};
    for (int i = 0; i < Qq; i++)
        for (int j = i + 1; j < Qq; j++)
            if (nrm[idx[j]] > nrm[idx[i]]) { int t = idx[i]; idx[i] = idx[j]; idx[j] = t; }
    for (int k = 0; k < Qq; k++) {
        int j = idx[k];
        float inv = (nrm[j] > 0.0) ? (float)(1.0 / nrm[j]) : 0.f;
        for (int n = tid; n < Nn; n += 1024) V[n * Qq + k] = M[n * Qq + j] * inv;
    }
}

// ---------------- matvec y = aa @ v (v strided) ----------------
__global__ void matvec_kernel(const float* __restrict__ aa, const float* __restrict__ v, int vs,
                              float* __restrict__ y) {
    __shared__ float sm[128];
    int n = blockIdx.x;
    const float* row = aa + (size_t)n * Nn;
    float p = 0.f;
    for (int k = threadIdx.x; k < Nn; k += 128) p += row[k] * v[k * vs];
    sm[threadIdx.x] = p; __syncthreads();
    for (int o = 64; o; o >>= 1) { if (threadIdx.x < o) sm[threadIdx.x] += sm[threadIdx.x + o]; __syncthreads(); }
    if (threadIdx.x == 0) y[n] = sm[0];
}

// ---------------- batched matvec: 3 strided columns of V ----------------
__global__ void matvec3s_kernel(const float* __restrict__ aa, const float* __restrict__ V,
                                float* __restrict__ y0, float* __restrict__ y1, float* __restrict__ y2) {
    __shared__ float sm[3][128];
    int n = blockIdx.x, tid = threadIdx.x;
    const float* row = aa + (size_t)n * Nn;
    float p0 = 0.f, p1 = 0.f, p2 = 0.f;
    for (int k = tid; k < Nn; k += 128) {
        float a = row[k];
        p0 += a * V[k * Qq + 0];
        p1 += a * V[k * Qq + 1];
        p2 += a * V[k * Qq + 2];
    }
    sm[0][tid] = p0; sm[1][tid] = p1; sm[2][tid] = p2;
    __syncthreads();
    for (int o = 64; o; o >>= 1) {
        if (tid < o) { sm[0][tid] += sm[0][tid + o]; sm[1][tid] += sm[1][tid + o]; sm[2][tid] += sm[2][tid + o]; }
        __syncthreads();
    }
    if (tid == 0) { y0[n] = sm[0][0]; y1[n] = sm[1][0]; y2[n] = sm[2][0]; }
}

// ---------------- batched matvec: 3 packed vectors ----------------
__global__ void matvec3p_kernel(const float* __restrict__ aa,
                                const float* __restrict__ v0, const float* __restrict__ v1,
                                const float* __restrict__ v2,
                                float* __restrict__ y0, float* __restrict__ y1, float* __restrict__ y2) {
    __shared__ float sm[3][128];
    int n = blockIdx.x, tid = threadIdx.x;
    const float* row = aa + (size_t)n * Nn;
    float p0 = 0.f, p1 = 0.f, p2 = 0.f;
    for (int k = tid; k < Nn; k += 128) {
        float a = row[k];
        p0 += a * v0[k];
        p1 += a * v1[k];
        p2 += a * v2[k];
    }
    sm[0][tid] = p0; sm[1][tid] = p1; sm[2][tid] = p2;
    __syncthreads();
    for (int o = 64; o; o >>= 1) {
        if (tid < o) { sm[0][tid] += sm[0][tid + o]; sm[1][tid] += sm[1][tid + o]; sm[2][tid] += sm[2][tid + o]; }
        __syncthreads();
    }
    if (tid == 0) { y0[n] = sm[0][0]; y1[n] = sm[1][0]; y2[n] = sm[2][0]; }
}

// ---------------- partial dots (no atomics, no prezero) ----------------
__global__ void dots_part_kernel(const float* __restrict__ w, const float* __restrict__ t,
                                 double* __restrict__ part) {
    __shared__ double s1[256], s2[256];
    int tid = threadIdx.x;
    int i = blockIdx.x * 256 + tid;
    double wv = w[i], tv = t[i];
    s1[tid] = wv * wv; s2[tid] = wv * tv;
    __syncthreads();
    for (int o = 128; o; o >>= 1) {
        if (tid < o) { s1[tid] += s1[tid + o]; s2[tid] += s2[tid + o]; }
        __syncthreads();
    }
    if (tid == 0) { part[blockIdx.x * 2] = s1[0]; part[blockIdx.x * 2 + 1] = s2[0]; }
}

__global__ void nuc_update2_kernel(const double* __restrict__ part, double* __restrict__ nuc,
                                   double* __restrict__ inv) {
    double ww = 0.0, wt = 0.0;
    for (int b = 0; b < 16; b++) { ww += part[b * 2]; wt += part[b * 2 + 1]; }
    ww = fmax(ww, 1e-300);
    *nuc += sqrt(fabs(wt / ww));
    *inv = 1.0 / ww;
}

// mode 0: aa *= (1 - vi vi^T) elementwise; mode 1: aa -= (aa vi) vi^T
__global__ void deflate4_kernel(float4* __restrict__ aa, const float* __restrict__ w,
                                const float* __restrict__ t, const double* __restrict__ inv_p,
                                int mode) {
    int idx = blockIdx.x * 256 + threadIdx.x;
    int i = idx >> 10;
    int j4 = (idx & 1023) << 2;
    float inv = (float)(*inv_p);
    float4 v = aa[idx];
    if (mode == 0) {
        float wi = w[i] * inv;
        v.x *= (1.f - wi * w[j4 + 0]);
        v.y *= (1.f - wi * w[j4 + 1]);
        v.z *= (1.f - wi * w[j4 + 2]);
        v.w *= (1.f - wi * w[j4 + 3]);
    } else {
        float ti = t[i] * inv;
        v.x -= ti * w[j4 + 0];
        v.y -= ti * w[j4 + 1];
        v.z -= ti * w[j4 + 2];
        v.w -= ti * w[j4 + 3];
    }
    aa[idx] = v;
}

__global__ void final_kernel(const float* __restrict__ red, const double* __restrict__ dred,
                             float* __restrict__ o_loss, float* __restrict__ o_calib) {
    float inv = 1.f / (float)Ee;
    float m1 = red[0] * inv, m2 = red[2] * inv;
    float c1 = red[1] * inv - m1 * m1;
    float c2 = red[3] * inv - m2 * m2;
    *o_loss = 0.01f * (c1 + c2) + 0.01f * (float)(dred[2] + dred[10]);
    *o_calib = red[5] / (float)Nn;
}

// ---------------- host orchestration ----------------
static void run_svd_nuc(const float* sd, const float* omega, float* aa, int mode,
                        float* Y, float* Z, float* Bt, float* V, float* W, float* T,
                        double* dredp, double* nuc, double* inv, cudaStream_t st) {
    matA_X_kernel<<<Nn, 128, 0, st>>>(sd, omega, Y);
    qr6f_kernel<<<1, 1024, 0, st>>>(Y);
    for (int it = 0; it < 2; it++) {
        fill_kernel<<<(Nn * Qq + 255) / 256, 256, 0, st>>>(Z, 0.f, Nn * Qq);
        matAT_X_kernel<<<dim3(Nn / 128, 8), 128, 0, st>>>(sd, Y, Z);
        qr6f_kernel<<<1, 1024, 0, st>>>(Z);
        matA_X_kernel<<<Nn, 128, 0, st>>>(sd, Z, Y);
        qr6f_kernel<<<1, 1024, 0, st>>>(Y);
    }
    fill_kernel<<<(Nn * Qq + 255) / 256, 256, 0, st>>>(Bt, 0.f, Nn * Qq);
    matAT_X_kernel<<<dim3(Nn / 128, 8), 128, 0, st>>>(sd, Y, Bt);
    osj_kernel<<<1, 1024, 0, st>>>(Bt, V);

    // nuc: k = 0..2 batched against undeflated aa
    matvec3s_kernel<<<Nn, 128, 0, st>>>(aa, V, W, W + Nn, W + 2 * Nn);
    matvec3p_kernel<<<Nn, 128, 0, st>>>(aa, W, W + Nn, W + 2 * Nn, T, T + Nn, T + 2 * Nn);
    for (int k = 0; k < 3; k++) {
        dots_part_kernel<<<16, 256, 0, st>>>(W + k * Nn, T + k * Nn, dredp);
        nuc_update2_kernel<<<1, 1, 0, st>>>(dredp, nuc, inv);
    }
    deflate4_kernel<<<(Nn * Nn / 4) / 256, 256, 0, st>>>((float4*)aa, W + 2 * Nn, T + 2 * Nn, inv, mode);
    for (int k = 3; k < Qq; k++) {
        matvec_kernel<<<Nn, 128, 0, st>>>(aa, V + k, Qq, W);
        matvec_kernel<<<Nn, 128, 0, st>>>(aa, W, 1, T);
        dots_part_kernel<<<16, 256, 0, st>>>(W, T, dredp);
        nuc_update2_kernel<<<1, 1, 0, st>>>(dredp, nuc, inv);
        if (k < 5)
            deflate4_kernel<<<(Nn * Nn / 4) / 256, 256, 0, st>>>((float4*)aa, W, T, inv, mode);
    }
}

extern "C" void kernel_launch(void* const* d_in, const int* in_sizes, int n_in,
                              void* d_out, int out_size) {
    const float* x      = (const float*)d_in[0];
    const int*   ei     = (const int*)d_in[1];
    const float* gcn1_w = (const float*)d_in[2];
    const float* gcn1_b = (const float*)d_in[3];
    const float* gcn2_w = (const float*)d_in[4];
    const float* gcn2_b = (const float*)d_in[5];
    const float* p1w1   = (const float*)d_in[6];
    const float* p1b1   = (const float*)d_in[7];
    const float* p1w2   = (const float*)d_in[8];
    const float* p1b2   = (const float*)d_in[9];
    const float* p2w1   = (const float*)d_in[10];
    const float* p2b1   = (const float*)d_in[11];
    const float* p2w2   = (const float*)d_in[12];
    const float* p2b2   = (const float*)d_in[13];
    const float* om1    = (const float*)d_in[14];
    const float* om2    = (const float*)d_in[15];

    float* out     = (float*)d_out;
    float* o_log   = out;                       // N*C
    float* o_sm    = out + Nn * Cc;             // N*C
    float* o_loss  = out + 2 * Nn * Cc;         // 1
    float* o_s1    = o_loss + 1;                // E
    float* o_s2    = o_s1 + Ee;                 // E
    float* o_calib = o_s2 + Ee;                 // 1

    float *s1d, *s2d, *aa1, *aa2, *h1, *x1, *hc, *xout, *deg, *Y, *Z, *Bt, *V, *wv, *tv, *red, *sg1, *sg2;
    double *dred, *dredp;
    cudaGetSymbolAddress((void**)&s1d, g_s1d);
    cudaGetSymbolAddress((void**)&s2d, g_s2d);
    cudaGetSymbolAddress((void**)&aa1, g_aa1);
    cudaGetSymbolAddress((void**)&aa2, g_aa2);
    cudaGetSymbolAddress((void**)&h1, g_h1);
    cudaGetSymbolAddress((void**)&x1, g_x1);
    cudaGetSymbolAddress((void**)&hc, g_hc);
    cudaGetSymbolAddress((void**)&xout, g_xout);
    cudaGetSymbolAddress((void**)&deg, g_deg);
    cudaGetSymbolAddress((void**)&Y, g_Y);
    cudaGetSymbolAddress((void**)&Z, g_Z);
    cudaGetSymbolAddress((void**)&Bt, g_Bt);
    cudaGetSymbolAddress((void**)&V, g_V);
    cudaGetSymbolAddress((void**)&wv, g_w);
    cudaGetSymbolAddress((void**)&tv, g_t);
    cudaGetSymbolAddress((void**)&red, g_red);
    cudaGetSymbolAddress((void**)&sg1, g_sg1);
    cudaGetSymbolAddress((void**)&sg2, g_sg2);
    cudaGetSymbolAddress((void**)&dred, g_dred);
    cudaGetSymbolAddress((void**)&dredp, g_dredp);

    static cudaStream_t sA = 0, sB = 0;
    static cudaEvent_t evS, evG1, evG2, evA, evB;
    if (!sA) {
        cudaStreamCreateWithFlags(&sA, cudaStreamNonBlocking);
        cudaStreamCreateWithFlags(&sB, cudaStreamNonBlocking);
        cudaEventCreateWithFlags(&evS, cudaEventDisableTiming);
        cudaEventCreateWithFlags(&evG1, cudaEventDisableTiming);
        cudaEventCreateWithFlags(&evG2, cudaEventDisableTiming);
        cudaEventCreateWithFlags(&evA, cudaEventDisableTiming);
        cudaEventCreateWithFlags(&evB, cudaEventDisableTiming);
    }

    zero_red_kernel<<<1, 32>>>(red, dred);

    // fork side streams; big adjacency fills overlap the gate phase
    cudaEventRecord(evS, 0);
    cudaStreamWaitEvent(sA, evS, 0);
    cudaStreamWaitEvent(sB, evS, 0);
    fill4_kernel<<<(Nn * Nn / 4) / 256, 256, 0, sA>>>((float4*)s1d, 1e-6f, Nn * Nn / 4);
    fill4_kernel<<<(Nn * Nn / 4) / 256, 256, 0, sB>>>((float4*)s2d, 1e-6f, Nn * Nn / 4);

    // gate 1 (internal buffer)
    gate1_kernel<<<Ee / 16, 256>>>(x, ei, p1w1, p1b1, p1w2, p1b2, sg1);
    cudaEventRecord(evG1, 0);

    // GCN conv 1
    xw_kernel<FIN, Hh><<<(Nn * Hh + 255) / 256, 256>>>(x, gcn1_w, h1);
    fill_kernel<<<(Nn + 255) / 256, 256>>>(deg, 1.0f, Nn);
    deg_acc_kernel<<<Ee / 256, 256>>>(ei, sg1, deg);
    deg_rsqrt_kernel<<<(Nn + 255) / 256, 256>>>(deg);
    init_out_kernel<Hh><<<(Nn * Hh + 255) / 256, 256>>>(h1, deg, x1);
    scatter_kernel<Hh><<<(Ee * Hh + 255) / 256, 256>>>(ei, sg1, deg, h1, x1);
    bias_act_kernel<Hh, 1><<<(Nn * Hh + 255) / 256, 256>>>(x1, gcn1_b);

    // gate 2 (internal buffer)
    gate2_kernel<<<Ee / 8, 256>>>(x1, ei, p2w1, p2b1, p2w2, p2b2, sg2);
    cudaEventRecord(evG2, 0);

    int ntile = Nn / 128;
    int ngrid = ntile * (ntile + 1) / 2;

    // branch A: adjacency 1 -> syrk -> svd+nuc (depends only on sg1)
    cudaStreamWaitEvent(sA, evG1, 0);
    scatter_dense_kernel<<<Ee / 256, 256, 0, sA>>>(ei, sg1, s1d);
    syrk_tc_kernel<<<ngrid, 256, 0, sA>>>(s1d, aa1);
    run_svd_nuc(s1d, om1, aa1, 0, Y, Z, Bt, V, wv, tv,
                dredp, &dred[2], &dred[3], sA);

    // branch B: adjacency 2 -> syrk -> svd+nuc (depends only on sg2)
    cudaStreamWaitEvent(sB, evG2, 0);
    scatter_dense_kernel<<<Ee / 256, 256, 0, sB>>>(ei, sg2, s2d);
    syrk_tc_kernel<<<ngrid, 256, 0, sB>>>(s2d, aa2);
    run_svd_nuc(s2d, om2, aa2, 1, Y + Nn * Qq, Z + Nn * Qq, Bt + Nn * Qq, V + Nn * Qq,
                wv + 3 * Nn, tv + 3 * Nn, dredp + 32, &dred[10], &dred[11], sB);

    // default stream: GCN conv 2 + softmax/consist (overlaps branches)
    xw_kernel<Hh, Cc><<<(Nn * Cc + 255) / 256, 256>>>(x1, gcn2_w, hc);
    fill_kernel<<<(Nn + 255) / 256, 256>>>(deg, 1.0f, Nn);
    deg_acc_kernel<<<Ee / 256, 256>>>(ei, sg2, deg);
    deg_rsqrt_kernel<<<(Nn + 255) / 256, 256>>>(deg);
    init_out_kernel<Cc><<<(Nn * Cc + 255) / 256, 256>>>(hc, deg, xout);
    scatter_kernel<Cc><<<(Ee * Cc + 255) / 256, 256>>>(ei, sg2, deg, hc, xout);
    bias_act_kernel<Cc, 0><<<(Nn * Cc + 255) / 256, 256>>>(xout, gcn2_b);
    softmax_kernel<<<Nn / 128, 128>>>(xout, o_log, o_sm, red);
    consist_kernel<<<Ee / 256, 256>>>(sg1, sg2, red);
    copy2_kernel<<<Ee / 256, 256>>>(sg1, o_s1, sg2, o_s2);

    // join
    cudaEventRecord(evA, sA);
    cudaEventRecord(evB, sB);
    cudaStreamWaitEvent(0, evA, 0);
    cudaStreamWaitEvent(0, evB, 0);

    final_kernel<<<1, 1>>>(red, dred, o_loss, o_calib);
}

// round 16
// speedup vs baseline: 1.0371x; 1.0371x over previous
#include <cuda_runtime.h>
#include <math.h>
#include <stdint.h>

#define Nn 4096
#define Ee 131072
#define FIN 512
#define Hh 64
#define Cc 16
#define Qq 6

// ---------------- scratch (static device memory; no allocations) ----------------
__device__ float g_s1d[Nn * Nn];
__device__ float g_s2d[Nn * Nn];
__device__ float g_aa1[Nn * Nn];
__device__ float g_aa2[Nn * Nn];
__device__ float g_h1[Nn * Hh];
__device__ float g_x1[Nn * Hh];
__device__ float g_hc[Nn * Cc];
__device__ float g_xout[Nn * Cc];
__device__ float g_deg[Nn];
__device__ float g_Y[2 * Nn * Qq];
__device__ float g_Z[2 * Nn * Qq];
__device__ float g_Bt[2 * Nn * Qq];
__device__ float g_V[2 * Nn * Qq];
__device__ float g_w[2 * 3 * Nn];
__device__ float g_t[2 * 3 * Nn];
__device__ float g_sg1[Ee];
__device__ float g_sg2[Ee];
__device__ float g_red[16];     // 0 sum_s1, 1 sumsq_s1, 2 sum_s2, 3 sumsq_s2, 5 calib
__device__ double g_dred[16];   // per run r: [8r+2]=nuc, [8r+3]=inv_ww
__device__ double g_dredp[2 * 32];  // per-run dot partials (16 blocks x 2)

// ---------------- utility ----------------
__global__ void fill_kernel(float* __restrict__ p, float v, int n) {
    int idx = blockIdx.x * blockDim.x + threadIdx.x;
    if (idx < n) p[idx] = v;
}

__global__ void fill4_kernel(float4* __restrict__ p, float v, int n4) {
    int idx = blockIdx.x * blockDim.x + threadIdx.x;
    if (idx < n4) p[idx] = make_float4(v, v, v, v);
}

__global__ void zero_red_kernel(float* red, double* dred) {
    if (threadIdx.x < 16) red[threadIdx.x] = 0.f;
    if (threadIdx.x < 16) dred[threadIdx.x] = 0.0;
}

__global__ void copy2_kernel(const float* __restrict__ a, float* __restrict__ oa,
                             const float* __restrict__ b, float* __restrict__ ob) {
    int i = blockIdx.x * blockDim.x + threadIdx.x;
    if (i < Ee) { oa[i] = a[i]; ob[i] = b[i]; }
}

// ---------------- edge gate 1: 512 -> 64 -> 1 MLP, 4 edges per thread ----------------
__global__ void gate1_kernel(const float* __restrict__ x, const int* __restrict__ ei,
                             const float* __restrict__ w1, const float* __restrict__ b1,
                             const float* __restrict__ w2, const float* __restrict__ b2,
                             float* __restrict__ sout) {
    __shared__ float sred[8][4];
    int tid = threadIdx.x;
    int j = tid & 63;
    int g = tid >> 6;                 // 0..3, 4 edges each -> 16 edges per block
    int e0 = blockIdx.x * 16 + g * 4;
    const float* xs0 = x + (size_t)ei[e0 + 0] * FIN;
    const float* xs1 = x + (size_t)ei[e0 + 1] * FIN;
    const float* xs2 = x + (size_t)ei[e0 + 2] * FIN;
    const float* xs3 = x + (size_t)ei[e0 + 3] * FIN;
    const float* xd0 = x + (size_t)ei[Ee + e0 + 0] * FIN;
    const float* xd1 = x + (size_t)ei[Ee + e0 + 1] * FIN;
    const float* xd2 = x + (size_t)ei[Ee + e0 + 2] * FIN;
    const float* xd3 = x + (size_t)ei[Ee + e0 + 3] * FIN;
    float bb = b1[j];
    float a0 = bb, a1 = bb, a2 = bb, a3 = bb;
#pragma unroll 4
    for (int f = 0; f < FIN; f++) {
        float w = w1[f * Hh + j];
        a0 += (xs0[f] - xd0[f]) * w;
        a1 += (xs1[f] - xd1[f]) * w;
        a2 += (xs2[f] - xd2[f]) * w;
        a3 += (xs3[f] - xd3[f]) * w;
    }
    float w2j = w2[j];
    float p0 = fmaxf(a0, 0.f) * w2j;
    float p1 = fmaxf(a1, 0.f) * w2j;
    float p2 = fmaxf(a2, 0.f) * w2j;
    float p3 = fmaxf(a3, 0.f) * w2j;
    for (int o = 16; o; o >>= 1) {
        p0 += __shfl_down_sync(0xffffffffu, p0, o);
        p1 += __shfl_down_sync(0xffffffffu, p1, o);
        p2 += __shfl_down_sync(0xffffffffu, p2, o);
        p3 += __shfl_down_sync(0xffffffffu, p3, o);
    }
    int wrp = tid >> 5;
    if ((tid & 31) == 0) { sred[wrp][0] = p0; sred[wrp][1] = p1; sred[wrp][2] = p2; sred[wrp][3] = p3; }
    __syncthreads();
    if (tid < 16) {
        int gg = tid >> 2, r = tid & 3;
        float agg = sred[2 * gg][r] + sred[2 * gg + 1][r] + b2[0];
        agg *= agg;
        float s = 1.f / (1.f + expf(-agg));
        sout[blockIdx.x * 16 + gg * 4 + r] = fminf(fmaxf(s, 0.f), 1.f);
    }
}

// ---------------- edge gate 2: 64 -> 32 -> 1 (warp per edge) ----------------
__global__ void gate2_kernel(const float* __restrict__ x1, const int* __restrict__ ei,
                             const float* __restrict__ w1, const float* __restrict__ b1,
                             const float* __restrict__ w2, const float* __restrict__ b2,
                             float* __restrict__ sout) {
    int wrp = threadIdx.x >> 5, lane = threadIdx.x & 31;
    int e = blockIdx.x * 8 + wrp;
    const float* xs = x1 + (size_t)ei[e] * Hh;
    const float* xd = x1 + (size_t)ei[Ee + e] * Hh;
    float acc = b1[lane];
#pragma unroll
    for (int f = 0; f < Hh; f++)
        acc += (xs[f] - xd[f]) * w1[f * 32 + lane];
    float p = fmaxf(acc, 0.f) * w2[lane];
    for (int o = 16; o; o >>= 1) p += __shfl_down_sync(0xffffffffu, p, o);
    if (lane == 0) {
        float agg = p + b2[0];
        agg *= agg;
        float s = 1.f / (1.f + expf(-agg));
        sout[e] = fminf(fmaxf(s, 0.f), 1.f);
    }
}

// ---------------- dense x @ W ----------------
template <int FI, int FO>
__global__ void xw_kernel(const float* __restrict__ x, const float* __restrict__ W,
                          float* __restrict__ out) {
    int idx = blockIdx.x * blockDim.x + threadIdx.x;
    if (idx >= Nn * FO) return;
    int n = idx / FO, j = idx % FO;
    const float* xr = x + (size_t)n * FI;
    float acc = 0.f;
#pragma unroll 8
    for (int f = 0; f < FI; f++)
        acc += xr[f] * W[f * FO + j];
    out[idx] = acc;
}

// ---------------- GCN aggregation helpers ----------------
__global__ void deg_acc_kernel(const int* __restrict__ ei, const float* __restrict__ s,
                               float* __restrict__ deg) {
    int e = blockIdx.x * blockDim.x + threadIdx.x;
    if (e < Ee) atomicAdd(&deg[ei[Ee + e]], s[e]);
}

__global__ void deg_rsqrt_kernel(float* __restrict__ deg) {
    int i = blockIdx.x * blockDim.x + threadIdx.x;
    if (i < Nn) deg[i] = rsqrtf(deg[i]);   // deg >= 1 (self loop)
}

template <int F>
__global__ void init_out_kernel(const float* __restrict__ h, const float* __restrict__ dis,
                                float* __restrict__ out) {
    int idx = blockIdx.x * blockDim.x + threadIdx.x;
    if (idx >= Nn * F) return;
    int n = idx / F;
    float d = dis[n];
    out[idx] = d * d * h[idx];
}

template <int F>
__global__ void scatter_kernel(const int* __restrict__ ei, const float* __restrict__ s,
                               const float* __restrict__ dis, const float* __restrict__ h,
                               float* __restrict__ out) {
    int idx = blockIdx.x * blockDim.x + threadIdx.x;
    if (idx >= Ee * F) return;
    int e = idx / F, f = idx % F;
    int si = ei[e], di = ei[Ee + e];
    float nrm = dis[si] * s[e] * dis[di];
    atomicAdd(&out[(size_t)di * F + f], nrm * h[(size_t)si * F + f]);
}

template <int F, int RELU>
__global__ void bias_act_kernel(float* __restrict__ p, const float* __restrict__ b) {
    int idx = blockIdx.x * blockDim.x + threadIdx.x;
    if (idx >= Nn * F) return;
    float v = p[idx] + b[idx % F];
    p[idx] = RELU ? fmaxf(v, 0.f) : v;
}

// ---------------- softmax + top2 ----------------
__global__ void softmax_kernel(const float* __restrict__ xo, float* __restrict__ olog,
                               float* __restrict__ osm, float* __restrict__ red) {
    int n = blockIdx.x * blockDim.x + threadIdx.x;
    if (n >= Nn) return;
    float v[Cc];
    float m1 = -1e30f, m2 = -1e30f;
#pragma unroll
    for (int c = 0; c < Cc; c++) {
        float a = xo[n * Cc + c];
        v[c] = a;
        if (a > m1) { m2 = m1; m1 = a; }
        else if (a > m2) m2 = a;
    }
    float se = 0.f;
#pragma unroll
    for (int c = 0; c < Cc; c++) se += expf(v[c] - m1);
    float lse = logf(se);
#pragma unroll
    for (int c = 0; c < Cc; c++) {
        olog[n * Cc + c] = v[c] - m1 - lse;
        osm[n * Cc + c] = expf(v[c] - m1) / se;
    }
    atomicAdd(&red[5], m2 - m1);   // calib = -top1 + top2
}

// ---------------- consist reductions ----------------
__global__ void consist_kernel(const float* __restrict__ s1, const float* __restrict__ s2,
                               float* __restrict__ red) {
    __shared__ float sm[256];
    int tid = threadIdx.x;
    int idx = blockIdx.x * 256 + tid;
    float a = s1[idx], b = s2[idx];
    float vals[4] = {a, a * a, b, b * b};
#pragma unroll
    for (int v = 0; v < 4; v++) {
        sm[tid] = vals[v];
        __syncthreads();
        for (int o = 128; o; o >>= 1) { if (tid < o) sm[tid] += sm[tid + o]; __syncthreads(); }
        if (tid == 0) atomicAdd(&red[v], sm[0]);
        __syncthreads();
    }
}

// ---------------- dense adjacency scatter ----------------
__global__ void scatter_dense_kernel(const int* __restrict__ ei, const float* __restrict__ s,
                                     float* __restrict__ sd) {
    int e = blockIdx.x * blockDim.x + threadIdx.x;
    if (e < Ee) atomicAdd(&sd[(size_t)ei[e] * Nn + ei[Ee + e]], s[e]);
}

// ---------------- tf32 helpers ----------------
__device__ __forceinline__ uint32_t f2tf32(float x) {
    uint32_t u;
    asm("cvt.rna.tf32.f32 %0, %1;" : "=r"(u) : "f"(x));
    return u;
}

__device__ __forceinline__ void mma_tf32(float* c, const uint32_t* a, const uint32_t* b) {
    asm volatile(
        "mma.sync.aligned.m16n8k8.row.col.f32.tf32.tf32.f32 "
        "{%0,%1,%2,%3},{%4,%5,%6,%7},{%8,%9},{%0,%1,%2,%3};"
        : "+f"(c[0]), "+f"(c[1]), "+f"(c[2]), "+f"(c[3])
        : "r"(a[0]), "r"(a[1]), "r"(a[2]), "r"(a[3]), "r"(b[0]), "r"(b[1]));
}

// ---------------- SYRK (tensor cores, tf32): C = A A^T, lower-tri tiles + mirror ----------
__global__ void __launch_bounds__(256, 2)
syrk_tc_kernel(const float* __restrict__ A, float* __restrict__ C) {
    int t = blockIdx.x;
    int bi = 0;
    while ((bi + 1) * (bi + 2) / 2 <= t) bi++;
    int bj = t - bi * (bi + 1) / 2;          // bi >= bj
    int I = bi * 128, J = bj * 128;

    __shared__ uint32_t As[128][32];
    __shared__ uint32_t Bs[128][32];

    int tid = threadIdx.x;
    int wid = tid >> 5, lane = tid & 31;
    int warp_m = wid >> 1;
    int warp_n = wid & 1;
    int lr = lane >> 2;
    int lk = lane & 3;

    float acc[2][8][4];
#pragma unroll
    for (int tm = 0; tm < 2; tm++)
#pragma unroll
        for (int tn = 0; tn < 8; tn++)
#pragma unroll
            for (int i = 0; i < 4; i++) acc[tm][tn][i] = 0.f;

    for (int k0 = 0; k0 < Nn; k0 += 32) {
#pragma unroll
        for (int i = 0; i < 4; i++) {
            int li = tid + i * 256;
            int row = li >> 3;
            int kq = (li & 7) << 2;
            float4 va = *(const float4*)(A + (size_t)(I + row) * Nn + k0 + kq);
            float4 vb = *(const float4*)(A + (size_t)(J + row) * Nn + k0 + kq);
            int pc = (kq + ((row & 7) << 2)) & 31;
            As[row][pc + 0] = f2tf32(va.x); As[row][pc + 1] = f2tf32(va.y);
            As[row][pc + 2] = f2tf32(va.z); As[row][pc + 3] = f2tf32(va.w);
            Bs[row][pc + 0] = f2tf32(vb.x); Bs[row][pc + 1] = f2tf32(vb.y);
            Bs[row][pc + 2] = f2tf32(vb.z); Bs[row][pc + 3] = f2tf32(vb.w);
        }
        __syncthreads();
#pragma unroll
        for (int kk = 0; kk < 32; kk += 8) {
            uint32_t af[2][4];
#pragma unroll
            for (int tm = 0; tm < 2; tm++) {
                int r = warp_m * 32 + tm * 16 + lr;
                int sw = (lr << 2);
                int c1 = (kk + lk + sw) & 31;
                int c2 = (kk + lk + 4 + sw) & 31;
                af[tm][0] = As[r][c1];
                af[tm][1] = As[r + 8][c1];
                af[tm][2] = As[r][c2];
                af[tm][3] = As[r + 8][c2];
            }
            uint32_t bf[8][2];
#pragma unroll
            for (int tn = 0; tn < 8; tn++) {
                int c = warp_n * 64 + tn * 8 + lr;
                int sw = (lr << 2);
                bf[tn][0] = Bs[c][(kk + lk + sw) & 31];
                bf[tn][1] = Bs[c][(kk + lk + 4 + sw) & 31];
            }
#pragma unroll
            for (int tm = 0; tm < 2; tm++)
#pragma unroll
                for (int tn = 0; tn < 8; tn++)
                    mma_tf32(acc[tm][tn], af[tm], bf[tn]);
        }
        __syncthreads();
    }

#pragma unroll
    for (int tm = 0; tm < 2; tm++) {
#pragma unroll
        for (int tn = 0; tn < 8; tn++) {
            int r = I + warp_m * 32 + tm * 16 + lr;
            int c = J + warp_n * 64 + tn * 8 + (lk << 1);
            C[(size_t)r * Nn + c] = acc[tm][tn][0];
            C[(size_t)r * Nn + c + 1] = acc[tm][tn][1];
            C[(size_t)(r + 8) * Nn + c] = acc[tm][tn][2];
            C[(size_t)(r + 8) * Nn + c + 1] = acc[tm][tn][3];
            if (bi != bj) {
                C[(size_t)c * Nn + r] = acc[tm][tn][0];
                C[(size_t)(c + 1) * Nn + r] = acc[tm][tn][1];
                C[(size_t)c * Nn + r + 8] = acc[tm][tn][2];
                C[(size_t)(c + 1) * Nn + r + 8] = acc[tm][tn][3];
            }
        }
    }
}

// ---------------- Y = A @ X  (X is [N,6]) ----------------
__global__ void matA_X_kernel(const float* __restrict__ A, const float* __restrict__ X,
                              float* __restrict__ Y) {
    __shared__ float sm[128 * Qq];
    int n = blockIdx.x;
    int tid = threadIdx.x;
    float acc[Qq] = {0, 0, 0, 0, 0, 0};
    const float* row = A + (size_t)n * Nn;
    for (int k = tid; k < Nn; k += 128) {
        float a = row[k];
#pragma unroll
        for (int q = 0; q < Qq; q++) acc[q] += a * X[k * Qq + q];
    }
#pragma unroll
    for (int q = 0; q < Qq; q++) sm[tid * Qq + q] = acc[q];
    __syncthreads();
    for (int o = 64; o; o >>= 1) {
        if (tid < o)
#pragma unroll
            for (int q = 0; q < Qq; q++) sm[tid * Qq + q] += sm[(tid + o) * Qq + q];
        __syncthreads();
    }
    if (tid < Qq) Y[n * Qq + tid] = sm[tid];
}

// ---------------- Z += A^T @ X (grid.y splits k, atomic accumulate; Z prezeroed) ----------------
__global__ void matAT_X_kernel(const float* __restrict__ A, const float* __restrict__ X,
                               float* __restrict__ Z) {
    __shared__ float Xs[512 * Qq];
    int n = blockIdx.x * 128 + threadIdx.x;
    int k0 = blockIdx.y * 512;
    for (int i = threadIdx.x; i < 512 * Qq; i += 128) Xs[i] = X[k0 * Qq + i];
    __syncthreads();
    float acc[Qq] = {0, 0, 0, 0, 0, 0};
    for (int kk = 0; kk < 512; kk++) {
        float a = A[(size_t)(k0 + kk) * Nn + n];
#pragma unroll
        for (int q = 0; q < Qq; q++) acc[q] += a * Xs[kk * Qq + q];
    }
#pragma unroll
    for (int q = 0; q < Qq; q++) atomicAdd(&Z[n * Qq + q], acc[q]);
}

// ---------------- shuffle-based block reduction helpers (256 threads, fp64) ----------------
__device__ __forceinline__ double shfl_red_d(double v) {
    for (int o = 16; o; o >>= 1) v += __shfl_down_sync(0xffffffffu, v, o);
    return v;
}

// ---------------- single-block MGS QR on [N,6], 256 thr, fp64, shuffle reductions ----------
__global__ void qr6f_kernel(float* __restrict__ Y) {
    __shared__ double sp[8 * 5];        // 8 warps x up to 5 values
    __shared__ double coefs[8];
    int tid = threadIdx.x;
    int lane = tid & 31, wrp = tid >> 5;
    for (int j = 0; j < Qq; j++) {
        // column norm (fp64): warp shuffle + 1-thread fold (2 barriers)
        double p = 0.0;
        for (int n = tid; n < Nn; n += 256) { double v = Y[n * Qq + j]; p += v * v; }
        p = shfl_red_d(p);
        if (lane == 0) sp[wrp] = p;
        __syncthreads();
        if (tid == 0) {
            double s = 0.0;
            for (int w = 0; w < 8; w++) s += sp[w];
            coefs[0] = (s > 0.0) ? (1.0 / sqrt(s)) : 0.0;
        }
        __syncthreads();
        float inv = (float)coefs[0];
        for (int n = tid; n < Nn; n += 256) Y[n * Qq + j] *= inv;
        __syncthreads();
        int nl = Qq - 1 - j;
        if (nl > 0) {
            double d[5] = {0, 0, 0, 0, 0};
            for (int n = tid; n < Nn; n += 256) {
                double yj = Y[n * Qq + j];
                for (int l = 0; l < nl; l++) d[l] += yj * (double)Y[n * Qq + j + 1 + l];
            }
            for (int l = 0; l < nl; l++) {
                d[l] = shfl_red_d(d[l]);
                if (lane == 0) sp[wrp * 5 + l] = d[l];
            }
            __syncthreads();
            if (tid < nl) {
                double s = 0.0;
                for (int w = 0; w < 8; w++) s += sp[w * 5 + tid];
                coefs[tid] = s;
            }
            __syncthreads();
            for (int n = tid; n < Nn; n += 256) {
                float yj = Y[n * Qq + j];
                for (int l = 0; l < nl; l++)
                    Y[n * Qq + j + 1 + l] -= (float)coefs[l] * yj;
            }
            __syncthreads();
        }
    }
}

// ---------------- one-sided Jacobi SVD on M=[N,6], 256 thr, shuffle reductions ----------
__global__ void osj_kernel(float* __restrict__ M, float* __restrict__ V) {
    __shared__ double sp[8 * 3];
    __shared__ double rot[3];
    __shared__ double nrm[Qq];
    __shared__ int nrot;
    int tid = threadIdx.x;
    int lane = tid & 31, wrp = tid >> 5;
    for (int sweep = 0; sweep < 10; sweep++) {
        if (tid == 0) nrot = 0;
        __syncthreads();
        for (int p = 0; p < Qq - 1; p++) {
            for (int q = p + 1; q < Qq; q++) {
                double da = 0.0, db = 0.0, dg = 0.0;
                for (int n = tid; n < Nn; n += 256) {
                    double mp = M[n * Qq + p], mq = M[n * Qq + q];
                    da += mp * mp; db += mq * mq; dg += mp * mq;
                }
                da = shfl_red_d(da);
                db = shfl_red_d(db);
                dg = shfl_red_d(dg);
                if (lane == 0) { sp[wrp * 3 + 0] = da; sp[wrp * 3 + 1] = db; sp[wrp * 3 + 2] = dg; }
                __syncthreads();
                if (tid == 0) {
                    double a = 0.0, b = 0.0, g = 0.0;
                    for (int w = 0; w < 8; w++) { a += sp[w * 3]; b += sp[w * 3 + 1]; g += sp[w * 3 + 2]; }
                    double thr = 1e-15 * sqrt(fmax(a * b, 0.0));
                    if (fabs(g) > thr && fabs(g) > 0.0) {
                        double z = (b - a) / (2.0 * g);
                        double tt = ((z >= 0.0) ? 1.0 : -1.0) / (fabs(z) + sqrt(1.0 + z * z));
                        double c = 1.0 / sqrt(1.0 + tt * tt);
                        rot[0] = c; rot[1] = tt * c; rot[2] = 1.0;
                        nrot++;
                    } else rot[2] = 0.0;
                }
                __syncthreads();
                if (rot[2] != 0.0) {
                    float c = (float)rot[0], s = (float)rot[1];
                    for (int n = tid; n < Nn; n += 256) {
                        float mp = M[n * Qq + p], mq = M[n * Qq + q];
                        M[n * Qq + p] = c * mp - s * mq;
                        M[n * Qq + q] = s * mp + c * mq;
                    }
                }
                __syncthreads();
            }
        }
        if (nrot == 0) break;
        __syncthreads();
    }
    for (int j = 0; j < Qq; j++) {
        double d = 0.0;
        for (int n = tid; n < Nn; n += 256) { double m = M[n * Qq + j]; d += m * m; }
        d = shfl_red_d(d);
        if (lane == 0) sp[wrp] = d;
        __syncthreads();
        if (tid == 0) {
            double s = 0.0;
            for (int w = 0; w < 8; w++) s += sp[w];
            nrm[j] = sqrt(s);
        }
        __syncthreads();
    }
    int idx[Qq] = {0, 1, 2, 3, 4, 5};
    for (int i = 0; i < Qq; i++)
        for (int j = i + 1; j < Qq; j++)
            if (nrm[idx[j]] > nrm[idx[i]]) { int t = idx[i]; idx[i] = idx[j]; idx[j] = t; }
    for (int k = 0; k < Qq; k++) {
        int j = idx[k];
        float inv = (nrm[j] > 0.0) ? (float)(1.0 / nrm[j]) : 0.f;
        for (int n = tid; n < Nn; n += 256) V[n * Qq + k] = M[n * Qq + j] * inv;
    }
}

// ---------------- matvec y = aa @ v (v strided) ----------------
__global__ void matvec_kernel(const float* __restrict__ aa, const float* __restrict__ v, int vs,
                              float* __restrict__ y) {
    __shared__ float sm[128];
    int n = blockIdx.x;
    const float* row = aa + (size_t)n * Nn;
    float p = 0.f;
    for (int k = threadIdx.x; k < Nn; k += 128) p += row[k] * v[k * vs];
    sm[threadIdx.x] = p; __syncthreads();
    for (int o = 64; o; o >>= 1) { if (threadIdx.x < o) sm[threadIdx.x] += sm[threadIdx.x + o]; __syncthreads(); }
    if (threadIdx.x == 0) y[n] = sm[0];
}

// ---------------- batched matvec: 3 strided columns of V ----------------
__global__ void matvec3s_kernel(const float* __restrict__ aa, const float* __restrict__ V,
                                float* __restrict__ y0, float* __restrict__ y1, float* __restrict__ y2) {
    __shared__ float sm[3][128];
    int n = blockIdx.x, tid = threadIdx.x;
    const float* row = aa + (size_t)n * Nn;
    float p0 = 0.f, p1 = 0.f, p2 = 0.f;
    for (int k = tid; k < Nn; k += 128) {
        float a = row[k];
        p0 += a * V[k * Qq + 0];
        p1 += a * V[k * Qq + 1];
        p2 += a * V[k * Qq + 2];
    }
    sm[0][tid] = p0; sm[1][tid] = p1; sm[2][tid] = p2;
    __syncthreads();
    for (int o = 64; o; o >>= 1) {
        if (tid < o) { sm[0][tid] += sm[0][tid + o]; sm[1][tid] += sm[1][tid + o]; sm[2][tid] += sm[2][tid + o]; }
        __syncthreads();
    }
    if (tid == 0) { y0[n] = sm[0][0]; y1[n] = sm[1][0]; y2[n] = sm[2][0]; }
}

// ---------------- batched matvec: 3 packed vectors ----------------
__global__ void matvec3p_kernel(const float* __restrict__ aa,
                                const float* __restrict__ v0, const float* __restrict__ v1,
                                const float* __restrict__ v2,
                                float* __restrict__ y0, float* __restrict__ y1, float* __restrict__ y2) {
    __shared__ float sm[3][128];
    int n = blockIdx.x, tid = threadIdx.x;
    const float* row = aa + (size_t)n * Nn;
    float p0 = 0.f, p1 = 0.f, p2 = 0.f;
    for (int k = tid; k < Nn; k += 128) {
        float a = row[k];
        p0 += a * v0[k];
        p1 += a * v1[k];
        p2 += a * v2[k];
    }
    sm[0][tid] = p0; sm[1][tid] = p1; sm[2][tid] = p2;
    __syncthreads();
    for (int o = 64; o; o >>= 1) {
        if (tid < o) { sm[0][tid] += sm[0][tid + o]; sm[1][tid] += sm[1][tid + o]; sm[2][tid] += sm[2][tid + o]; }
        __syncthreads();
    }
    if (tid == 0) { y0[n] = sm[0][0]; y1[n] = sm[1][0]; y2[n] = sm[2][0]; }
}

// ---------------- partial dots (no atomics, no prezero) ----------------
__global__ void dots_part_kernel(const float* __restrict__ w, const float* __restrict__ t,
                                 double* __restrict__ part) {
    __shared__ double s1[256], s2[256];
    int tid = threadIdx.x;
    int i = blockIdx.x * 256 + tid;
    double wv = w[i], tv = t[i];
    s1[tid] = wv * wv; s2[tid] = wv * tv;
    __syncthreads();
    for (int o = 128; o; o >>= 1) {
        if (tid < o) { s1[tid] += s1[tid + o]; s2[tid] += s2[tid + o]; }
        __syncthreads();
    }
    if (tid == 0) { part[blockIdx.x * 2] = s1[0]; part[blockIdx.x * 2 + 1] = s2[0]; }
}

__global__ void nuc_update2_kernel(const double* __restrict__ part, double* __restrict__ nuc,
                                   double* __restrict__ inv) {
    double ww = 0.0, wt = 0.0;
    for (int b = 0; b < 16; b++) { ww += part[b * 2]; wt += part[b * 2 + 1]; }
    ww = fmax(ww, 1e-300);
    *nuc += sqrt(fabs(wt / ww));
    *inv = 1.0 / ww;
}

// mode 0: aa *= (1 - vi vi^T) elementwise; mode 1: aa -= (aa vi) vi^T
__global__ void deflate4_kernel(float4* __restrict__ aa, const float* __restrict__ w,
                                const float* __restrict__ t, const double* __restrict__ inv_p,
                                int mode) {
    int idx = blockIdx.x * 256 + threadIdx.x;
    int i = idx >> 10;
    int j4 = (idx & 1023) << 2;
    float inv = (float)(*inv_p);
    float4 v = aa[idx];
    if (mode == 0) {
        float wi = w[i] * inv;
        v.x *= (1.f - wi * w[j4 + 0]);
        v.y *= (1.f - wi * w[j4 + 1]);
        v.z *= (1.f - wi * w[j4 + 2]);
        v.w *= (1.f - wi * w[j4 + 3]);
    } else {
        float ti = t[i] * inv;
        v.x -= ti * w[j4 + 0];
        v.y -= ti * w[j4 + 1];
        v.z -= ti * w[j4 + 2];
        v.w -= ti * w[j4 + 3];
    }
    aa[idx] = v;
}

__global__ void final_kernel(const float* __restrict__ red, const double* __restrict__ dred,
                             float* __restrict__ o_loss, float* __restrict__ o_calib) {
    float inv = 1.f / (float)Ee;
    float m1 = red[0] * inv, m2 = red[2] * inv;
    float c1 = red[1] * inv - m1 * m1;
    float c2 = red[3] * inv - m2 * m2;
    *o_loss = 0.01f * (c1 + c2) + 0.01f * (float)(dred[2] + dred[10]);
    *o_calib = red[5] / (float)Nn;
}

// ---------------- host orchestration ----------------
static void run_svd_nuc(const float* sd, const float* omega, float* aa, int mode,
                        float* Y, float* Z, float* Bt, float* V, float* W, float* T,
                        double* dredp, double* nuc, double* inv, cudaStream_t st) {
    matA_X_kernel<<<Nn, 128, 0, st>>>(sd, omega, Y);
    qr6f_kernel<<<1, 256, 0, st>>>(Y);
    for (int it = 0; it < 2; it++) {
        fill_kernel<<<(Nn * Qq + 255) / 256, 256, 0, st>>>(Z, 0.f, Nn * Qq);
        matAT_X_kernel<<<dim3(Nn / 128, 8), 128, 0, st>>>(sd, Y, Z);
        qr6f_kernel<<<1, 256, 0, st>>>(Z);
        matA_X_kernel<<<Nn, 128, 0, st>>>(sd, Z, Y);
        qr6f_kernel<<<1, 256, 0, st>>>(Y);
    }
    fill_kernel<<<(Nn * Qq + 255) / 256, 256, 0, st>>>(Bt, 0.f, Nn * Qq);
    matAT_X_kernel<<<dim3(Nn / 128, 8), 128, 0, st>>>(sd, Y, Bt);
    osj_kernel<<<1, 256, 0, st>>>(Bt, V);

    // nuc: k = 0..2 batched against undeflated aa
    matvec3s_kernel<<<Nn, 128, 0, st>>>(aa, V, W, W + Nn, W + 2 * Nn);
    matvec3p_kernel<<<Nn, 128, 0, st>>>(aa, W, W + Nn, W + 2 * Nn, T, T + Nn, T + 2 * Nn);
    for (int k = 0; k < 3; k++) {
        dots_part_kernel<<<16, 256, 0, st>>>(W + k * Nn, T + k * Nn, dredp);
        nuc_update2_kernel<<<1, 1, 0, st>>>(dredp, nuc, inv);
    }
    deflate4_kernel<<<(Nn * Nn / 4) / 256, 256, 0, st>>>((float4*)aa, W + 2 * Nn, T + 2 * Nn, inv, mode);
    for (int k = 3; k < Qq; k++) {
        matvec_kernel<<<Nn, 128, 0, st>>>(aa, V + k, Qq, W);
        matvec_kernel<<<Nn, 128, 0, st>>>(aa, W, 1, T);
        dots_part_kernel<<<16, 256, 0, st>>>(W, T, dredp);
        nuc_update2_kernel<<<1, 1, 0, st>>>(dredp, nuc, inv);
        if (k < 5)
            deflate4_kernel<<<(Nn * Nn / 4) / 256, 256, 0, st>>>((float4*)aa, W, T, inv, mode);
    }
}

extern "C" void kernel_launch(void* const* d_in, const int* in_sizes, int n_in,
                              void* d_out, int out_size) {
    const float* x      = (const float*)d_in[0];
    const int*   ei     = (const int*)d_in[1];
    const float* gcn1_w = (const float*)d_in[2];
    const float* gcn1_b = (const float*)d_in[3];
    const float* gcn2_w = (const float*)d_in[4];
    const float* gcn2_b = (const float*)d_in[5];
    const float* p1w1   = (const float*)d_in[6];
    const float* p1b1   = (const float*)d_in[7];
    const float* p1w2   = (const float*)d_in[8];
    const float* p1b2   = (const float*)d_in[9];
    const float* p2w1   = (const float*)d_in[10];
    const float* p2b1   = (const float*)d_in[11];
    const float* p2w2   = (const float*)d_in[12];
    const float* p2b2   = (const float*)d_in[13];
    const float* om1    = (const float*)d_in[14];
    const float* om2    = (const float*)d_in[15];

    float* out     = (float*)d_out;
    float* o_log   = out;                       // N*C
    float* o_sm    = out + Nn * Cc;             // N*C
    float* o_loss  = out + 2 * Nn * Cc;         // 1
    float* o_s1    = o_loss + 1;                // E
    float* o_s2    = o_s1 + Ee;                 // E
    float* o_calib = o_s2 + Ee;                 // 1

    float *s1d, *s2d, *aa1, *aa2, *h1, *x1, *hc, *xout, *deg, *Y, *Z, *Bt, *V, *wv, *tv, *red, *sg1, *sg2;
    double *dred, *dredp;
    cudaGetSymbolAddress((void**)&s1d, g_s1d);
    cudaGetSymbolAddress((void**)&s2d, g_s2d);
    cudaGetSymbolAddress((void**)&aa1, g_aa1);
    cudaGetSymbolAddress((void**)&aa2, g_aa2);
    cudaGetSymbolAddress((void**)&h1, g_h1);
    cudaGetSymbolAddress((void**)&x1, g_x1);
    cudaGetSymbolAddress((void**)&hc, g_hc);
    cudaGetSymbolAddress((void**)&xout, g_xout);
    cudaGetSymbolAddress((void**)&deg, g_deg);
    cudaGetSymbolAddress((void**)&Y, g_Y);
    cudaGetSymbolAddress((void**)&Z, g_Z);
    cudaGetSymbolAddress((void**)&Bt, g_Bt);
    cudaGetSymbolAddress((void**)&V, g_V);
    cudaGetSymbolAddress((void**)&wv, g_w);
    cudaGetSymbolAddress((void**)&tv, g_t);
    cudaGetSymbolAddress((void**)&red, g_red);
    cudaGetSymbolAddress((void**)&sg1, g_sg1);
    cudaGetSymbolAddress((void**)&sg2, g_sg2);
    cudaGetSymbolAddress((void**)&dred, g_dred);
    cudaGetSymbolAddress((void**)&dredp, g_dredp);

    static cudaStream_t sA = 0, sB = 0;
    static cudaEvent_t evS, evG1, evG2, evA, evB;
    if (!sA) {
        cudaStreamCreateWithFlags(&sA, cudaStreamNonBlocking);
        cudaStreamCreateWithFlags(&sB, cudaStreamNonBlocking);
        cudaEventCreateWithFlags(&evS, cudaEventDisableTiming);
        cudaEventCreateWithFlags(&evG1, cudaEventDisableTiming);
        cudaEventCreateWithFlags(&evG2, cudaEventDisableTiming);
        cudaEventCreateWithFlags(&evA, cudaEventDisableTiming);
        cudaEventCreateWithFlags(&evB, cudaEventDisableTiming);
    }

    zero_red_kernel<<<1, 32>>>(red, dred);

    // fork side streams; big adjacency fills overlap the gate phase
    cudaEventRecord(evS, 0);
    cudaStreamWaitEvent(sA, evS, 0);
    cudaStreamWaitEvent(sB, evS, 0);
    fill4_kernel<<<(Nn * Nn / 4) / 256, 256, 0, sA>>>((float4*)s1d, 1e-6f, Nn * Nn / 4);
    fill4_kernel<<<(Nn * Nn / 4) / 256, 256, 0, sB>>>((float4*)s2d, 1e-6f, Nn * Nn / 4);

    // gate 1 (internal buffer)
    gate1_kernel<<<Ee / 16, 256>>>(x, ei, p1w1, p1b1, p1w2, p1b2, sg1);
    cudaEventRecord(evG1, 0);

    // GCN conv 1
    xw_kernel<FIN, Hh><<<(Nn * Hh + 255) / 256, 256>>>(x, gcn1_w, h1);
    fill_kernel<<<(Nn + 255) / 256, 256>>>(deg, 1.0f, Nn);
    deg_acc_kernel<<<Ee / 256, 256>>>(ei, sg1, deg);
    deg_rsqrt_kernel<<<(Nn + 255) / 256, 256>>>(deg);
    init_out_kernel<Hh><<<(Nn * Hh + 255) / 256, 256>>>(h1, deg, x1);
    scatter_kernel<Hh><<<(Ee * Hh + 255) / 256, 256>>>(ei, sg1, deg, h1, x1);
    bias_act_kernel<Hh, 1><<<(Nn * Hh + 255) / 256, 256>>>(x1, gcn1_b);

    // gate 2 (internal buffer)
    gate2_kernel<<<Ee / 8, 256>>>(x1, ei, p2w1, p2b1, p2w2, p2b2, sg2);
    cudaEventRecord(evG2, 0);

    int ntile = Nn / 128;
    int ngrid = ntile * (ntile + 1) / 2;

    // branch A: adjacency 1 -> syrk -> svd+nuc (depends only on sg1)
    cudaStreamWaitEvent(sA, evG1, 0);
    scatter_dense_kernel<<<Ee / 256, 256, 0, sA>>>(ei, sg1, s1d);
    syrk_tc_kernel<<<ngrid, 256, 0, sA>>>(s1d, aa1);
    run_svd_nuc(s1d, om1, aa1, 0, Y, Z, Bt, V, wv, tv,
                dredp, &dred[2], &dred[3], sA);

    // branch B: adjacency 2 -> syrk -> svd+nuc (depends only on sg2)
    cudaStreamWaitEvent(sB, evG2, 0);
    scatter_dense_kernel<<<Ee / 256, 256, 0, sB>>>(ei, sg2, s2d);
    syrk_tc_kernel<<<ngrid, 256, 0, sB>>>(s2d, aa2);
    run_svd_nuc(s2d, om2, aa2, 1, Y + Nn * Qq, Z + Nn * Qq, Bt + Nn * Qq, V + Nn * Qq,
                wv + 3 * Nn, tv + 3 * Nn, dredp + 32, &dred[10], &dred[11], sB);

    // default stream: GCN conv 2 + softmax/consist (overlaps branches)
    xw_kernel<Hh, Cc><<<(Nn * Cc + 255) / 256, 256>>>(x1, gcn2_w, hc);
    fill_kernel<<<(Nn + 255) / 256, 256>>>(deg, 1.0f, Nn);
    deg_acc_kernel<<<Ee / 256, 256>>>(ei, sg2, deg);
    deg_rsqrt_kernel<<<(Nn + 255) / 256, 256>>>(deg);
    init_out_kernel<Cc><<<(Nn * Cc + 255) / 256, 256>>>(hc, deg, xout);
    scatter_kernel<Cc><<<(Ee * Cc + 255) / 256, 256>>>(ei, sg2, deg, hc, xout);
    bias_act_kernel<Cc, 0><<<(Nn * Cc + 255) / 256, 256>>>(xout, gcn2_b);
    softmax_kernel<<<Nn / 128, 128>>>(xout, o_log, o_sm, red);
    consist_kernel<<<Ee / 256, 256>>>(sg1, sg2, red);
    copy2_kernel<<<Ee / 256, 256>>>(sg1, o_s1, sg2, o_s2);

    // join
    cudaEventRecord(evA, sA);
    cudaEventRecord(evB, sB);
    cudaStreamWaitEvent(0, evA, 0);
    cudaStreamWaitEvent(0, evB, 0);

    final_kernel<<<1, 1>>>(red, dred, o_loss, o_calib);
}

// round 17
// speedup vs baseline: 1.0482x; 1.0107x over previous
#include <cuda_runtime.h>
#include <math.h>
#include <stdint.h>

#define Nn 4096
#define Ee 131072
#define FIN 512
#define Hh 64
#define Cc 16
#define Qq 6

// ---------------- scratch (static device memory; no allocations) ----------------
__device__ float g_s1d[Nn * Nn];
__device__ float g_s2d[Nn * Nn];
__device__ float g_aa1[Nn * Nn];
__device__ float g_aa2[Nn * Nn];
__device__ float g_h1[Nn * Hh];
__device__ float g_x1[Nn * Hh];
__device__ float g_hc[Nn * Cc];
__device__ float g_xout[Nn * Cc];
__device__ float g_deg[Nn];
__device__ float g_Y[2 * Nn * Qq];
__device__ float g_Z[2 * Nn * Qq];
__device__ float g_Bt[2 * Nn * Qq];
__device__ float g_V[2 * Nn * Qq];
__device__ float g_w[2 * 3 * Nn];
__device__ float g_t[2 * 3 * Nn];
__device__ float g_sg1[Ee];
__device__ float g_sg2[Ee];
__device__ float g_red[16];     // 0 sum_s1, 1 sumsq_s1, 2 sum_s2, 3 sumsq_s2, 5 calib
__device__ double g_dred[16];   // per run r: [8r+2]=nuc, [8r+3]=inv_ww
__device__ double g_dredp[2 * 32];  // per-run dot partials (16 blocks x 2)

// ---------------- utility ----------------
__global__ void fill_kernel(float* __restrict__ p, float v, int n) {
    int idx = blockIdx.x * blockDim.x + threadIdx.x;
    if (idx < n) p[idx] = v;
}

__global__ void fill4_kernel(float4* __restrict__ p, float v, int n4) {
    int idx = blockIdx.x * blockDim.x + threadIdx.x;
    if (idx < n4) p[idx] = make_float4(v, v, v, v);
}

__global__ void zero_red_kernel(float* red, double* dred) {
    if (threadIdx.x < 16) red[threadIdx.x] = 0.f;
    if (threadIdx.x < 16) dred[threadIdx.x] = 0.0;
}

__global__ void copy2_kernel(const float* __restrict__ a, float* __restrict__ oa,
                             const float* __restrict__ b, float* __restrict__ ob) {
    int i = blockIdx.x * blockDim.x + threadIdx.x;
    if (i < Ee) { oa[i] = a[i]; ob[i] = b[i]; }
}

// ---------------- edge gate 1: 512 -> 64 -> 1 MLP, 4 edges per thread ----------------
__global__ void gate1_kernel(const float* __restrict__ x, const int* __restrict__ ei,
                             const float* __restrict__ w1, const float* __restrict__ b1,
                             const float* __restrict__ w2, const float* __restrict__ b2,
                             float* __restrict__ sout) {
    __shared__ float sred[8][4];
    int tid = threadIdx.x;
    int j = tid & 63;
    int g = tid >> 6;                 // 0..3, 4 edges each -> 16 edges per block
    int e0 = blockIdx.x * 16 + g * 4;
    const float* xs0 = x + (size_t)ei[e0 + 0] * FIN;
    const float* xs1 = x + (size_t)ei[e0 + 1] * FIN;
    const float* xs2 = x + (size_t)ei[e0 + 2] * FIN;
    const float* xs3 = x + (size_t)ei[e0 + 3] * FIN;
    const float* xd0 = x + (size_t)ei[Ee + e0 + 0] * FIN;
    const float* xd1 = x + (size_t)ei[Ee + e0 + 1] * FIN;
    const float* xd2 = x + (size_t)ei[Ee + e0 + 2] * FIN;
    const float* xd3 = x + (size_t)ei[Ee + e0 + 3] * FIN;
    float bb = b1[j];
    float a0 = bb, a1 = bb, a2 = bb, a3 = bb;
#pragma unroll 4
    for (int f = 0; f < FIN; f++) {
        float w = w1[f * Hh + j];
        a0 += (xs0[f] - xd0[f]) * w;
        a1 += (xs1[f] - xd1[f]) * w;
        a2 += (xs2[f] - xd2[f]) * w;
        a3 += (xs3[f] - xd3[f]) * w;
    }
    float w2j = w2[j];
    float p0 = fmaxf(a0, 0.f) * w2j;
    float p1 = fmaxf(a1, 0.f) * w2j;
    float p2 = fmaxf(a2, 0.f) * w2j;
    float p3 = fmaxf(a3, 0.f) * w2j;
    for (int o = 16; o; o >>= 1) {
        p0 += __shfl_down_sync(0xffffffffu, p0, o);
        p1 += __shfl_down_sync(0xffffffffu, p1, o);
        p2 += __shfl_down_sync(0xffffffffu, p2, o);
        p3 += __shfl_down_sync(0xffffffffu, p3, o);
    }
    int wrp = tid >> 5;
    if ((tid & 31) == 0) { sred[wrp][0] = p0; sred[wrp][1] = p1; sred[wrp][2] = p2; sred[wrp][3] = p3; }
    __syncthreads();
    if (tid < 16) {
        int gg = tid >> 2, r = tid & 3;
        float agg = sred[2 * gg][r] + sred[2 * gg + 1][r] + b2[0];
        agg *= agg;
        float s = 1.f / (1.f + expf(-agg));
        sout[blockIdx.x * 16 + gg * 4 + r] = fminf(fmaxf(s, 0.f), 1.f);
    }
}

// ---------------- edge gate 2: 64 -> 32 -> 1 (warp per edge) ----------------
__global__ void gate2_kernel(const float* __restrict__ x1, const int* __restrict__ ei,
                             const float* __restrict__ w1, const float* __restrict__ b1,
                             const float* __restrict__ w2, const float* __restrict__ b2,
                             float* __restrict__ sout) {
    int wrp = threadIdx.x >> 5, lane = threadIdx.x & 31;
    int e = blockIdx.x * 8 + wrp;
    const float* xs = x1 + (size_t)ei[e] * Hh;
    const float* xd = x1 + (size_t)ei[Ee + e] * Hh;
    float acc = b1[lane];
#pragma unroll
    for (int f = 0; f < Hh; f++)
        acc += (xs[f] - xd[f]) * w1[f * 32 + lane];
    float p = fmaxf(acc, 0.f) * w2[lane];
    for (int o = 16; o; o >>= 1) p += __shfl_down_sync(0xffffffffu, p, o);
    if (lane == 0) {
        float agg = p + b2[0];
        agg *= agg;
        float s = 1.f / (1.f + expf(-agg));
        sout[e] = fminf(fmaxf(s, 0.f), 1.f);
    }
}

// ---------------- dense x @ W ----------------
template <int FI, int FO>
__global__ void xw_kernel(const float* __restrict__ x, const float* __restrict__ W,
                          float* __restrict__ out) {
    int idx = blockIdx.x * blockDim.x + threadIdx.x;
    if (idx >= Nn * FO) return;
    int n = idx / FO, j = idx % FO;
    const float* xr = x + (size_t)n * FI;
    float acc = 0.f;
#pragma unroll 8
    for (int f = 0; f < FI; f++)
        acc += xr[f] * W[f * FO + j];
    out[idx] = acc;
}

// ---------------- GCN aggregation helpers ----------------
__global__ void deg_acc_kernel(const int* __restrict__ ei, const float* __restrict__ s,
                               float* __restrict__ deg) {
    int e = blockIdx.x * blockDim.x + threadIdx.x;
    if (e < Ee) atomicAdd(&deg[ei[Ee + e]], s[e]);
}

__global__ void deg_rsqrt_kernel(float* __restrict__ deg) {
    int i = blockIdx.x * blockDim.x + threadIdx.x;
    if (i < Nn) deg[i] = rsqrtf(deg[i]);   // deg >= 1 (self loop)
}

template <int F>
__global__ void init_out_kernel(const float* __restrict__ h, const float* __restrict__ dis,
                                float* __restrict__ out) {
    int idx = blockIdx.x * blockDim.x + threadIdx.x;
    if (idx >= Nn * F) return;
    int n = idx / F;
    float d = dis[n];
    out[idx] = d * d * h[idx];
}

template <int F>
__global__ void scatter_kernel(const int* __restrict__ ei, const float* __restrict__ s,
                               const float* __restrict__ dis, const float* __restrict__ h,
                               float* __restrict__ out) {
    int idx = blockIdx.x * blockDim.x + threadIdx.x;
    if (idx >= Ee * F) return;
    int e = idx / F, f = idx % F;
    int si = ei[e], di = ei[Ee + e];
    float nrm = dis[si] * s[e] * dis[di];
    atomicAdd(&out[(size_t)di * F + f], nrm * h[(size_t)si * F + f]);
}

template <int F, int RELU>
__global__ void bias_act_kernel(float* __restrict__ p, const float* __restrict__ b) {
    int idx = blockIdx.x * blockDim.x + threadIdx.x;
    if (idx >= Nn * F) return;
    float v = p[idx] + b[idx % F];
    p[idx] = RELU ? fmaxf(v, 0.f) : v;
}

// ---------------- softmax + top2 ----------------
__global__ void softmax_kernel(const float* __restrict__ xo, float* __restrict__ olog,
                               float* __restrict__ osm, float* __restrict__ red) {
    int n = blockIdx.x * blockDim.x + threadIdx.x;
    if (n >= Nn) return;
    float v[Cc];
    float m1 = -1e30f, m2 = -1e30f;
#pragma unroll
    for (int c = 0; c < Cc; c++) {
        float a = xo[n * Cc + c];
        v[c] = a;
        if (a > m1) { m2 = m1; m1 = a; }
        else if (a > m2) m2 = a;
    }
    float se = 0.f;
#pragma unroll
    for (int c = 0; c < Cc; c++) se += expf(v[c] - m1);
    float lse = logf(se);
#pragma unroll
    for (int c = 0; c < Cc; c++) {
        olog[n * Cc + c] = v[c] - m1 - lse;
        osm[n * Cc + c] = expf(v[c] - m1) / se;
    }
    atomicAdd(&red[5], m2 - m1);   // calib = -top1 + top2
}

// ---------------- consist reductions ----------------
__global__ void consist_kernel(const float* __restrict__ s1, const float* __restrict__ s2,
                               float* __restrict__ red) {
    __shared__ float sm[256];
    int tid = threadIdx.x;
    int idx = blockIdx.x * 256 + tid;
    float a = s1[idx], b = s2[idx];
    float vals[4] = {a, a * a, b, b * b};
#pragma unroll
    for (int v = 0; v < 4; v++) {
        sm[tid] = vals[v];
        __syncthreads();
        for (int o = 128; o; o >>= 1) { if (tid < o) sm[tid] += sm[tid + o]; __syncthreads(); }
        if (tid == 0) atomicAdd(&red[v], sm[0]);
        __syncthreads();
    }
}

// ---------------- dense adjacency scatter ----------------
__global__ void scatter_dense_kernel(const int* __restrict__ ei, const float* __restrict__ s,
                                     float* __restrict__ sd) {
    int e = blockIdx.x * blockDim.x + threadIdx.x;
    if (e < Ee) atomicAdd(&sd[(size_t)ei[e] * Nn + ei[Ee + e]], s[e]);
}

// ---------------- tf32 helpers ----------------
__device__ __forceinline__ uint32_t f2tf32(float x) {
    uint32_t u;
    asm("cvt.rna.tf32.f32 %0, %1;" : "=r"(u) : "f"(x));
    return u;
}

__device__ __forceinline__ void mma_tf32(float* c, const uint32_t* a, const uint32_t* b) {
    asm volatile(
        "mma.sync.aligned.m16n8k8.row.col.f32.tf32.tf32.f32 "
        "{%0,%1,%2,%3},{%4,%5,%6,%7},{%8,%9},{%0,%1,%2,%3};"
        : "+f"(c[0]), "+f"(c[1]), "+f"(c[2]), "+f"(c[3])
        : "r"(a[0]), "r"(a[1]), "r"(a[2]), "r"(a[3]), "r"(b[0]), "r"(b[1]));
}

// ---------------- SYRK (tensor cores, tf32, double-buffered): C = A A^T ----------
// Two smem stages; per panel: issue next LDGs -> compute current -> STS next -> 1 sync.
// Identical mma order/operands to the single-buffer version (bit-identical result).
__global__ void __launch_bounds__(256, 2)
syrk_tc_kernel(const float* __restrict__ A, float* __restrict__ C) {
    int t = blockIdx.x;
    int bi = 0;
    while ((bi + 1) * (bi + 2) / 2 <= t) bi++;
    int bj = t - bi * (bi + 1) / 2;          // bi >= bj
    int I = bi * 128, J = bj * 128;

    __shared__ uint32_t As[2][128][32];
    __shared__ uint32_t Bs[2][128][32];

    int tid = threadIdx.x;
    int wid = tid >> 5, lane = tid & 31;
    int warp_m = wid >> 1;
    int warp_n = wid & 1;
    int lr = lane >> 2;
    int lk = lane & 3;

    // per-thread load coordinates (4 chunks of float4)
    int lrow[4], lkq[4], lpc[4];
#pragma unroll
    for (int i = 0; i < 4; i++) {
        int li = tid + i * 256;
        lrow[i] = li >> 3;
        lkq[i] = (li & 7) << 2;
        lpc[i] = (lkq[i] + ((lrow[i] & 7) << 2)) & 31;
    }

    float acc[2][8][4];
#pragma unroll
    for (int tm = 0; tm < 2; tm++)
#pragma unroll
        for (int tn = 0; tn < 8; tn++)
#pragma unroll
            for (int i = 0; i < 4; i++) acc[tm][tn][i] = 0.f;

    float4 ra[4], rb[4];
    // prologue: load panel 0 and stage into buffer 0
#pragma unroll
    for (int i = 0; i < 4; i++) {
        ra[i] = *(const float4*)(A + (size_t)(I + lrow[i]) * Nn + lkq[i]);
        rb[i] = *(const float4*)(A + (size_t)(J + lrow[i]) * Nn + lkq[i]);
    }
#pragma unroll
    for (int i = 0; i < 4; i++) {
        As[0][lrow[i]][lpc[i] + 0] = f2tf32(ra[i].x); As[0][lrow[i]][lpc[i] + 1] = f2tf32(ra[i].y);
        As[0][lrow[i]][lpc[i] + 2] = f2tf32(ra[i].z); As[0][lrow[i]][lpc[i] + 3] = f2tf32(ra[i].w);
        Bs[0][lrow[i]][lpc[i] + 0] = f2tf32(rb[i].x); Bs[0][lrow[i]][lpc[i] + 1] = f2tf32(rb[i].y);
        Bs[0][lrow[i]][lpc[i] + 2] = f2tf32(rb[i].z); Bs[0][lrow[i]][lpc[i] + 3] = f2tf32(rb[i].w);
    }
    __syncthreads();

    const int npan = Nn / 32;
    for (int p = 0; p < npan; p++) {
        int cur = p & 1;
        int hasNext = (p + 1 < npan);
        if (hasNext) {
            int k0 = (p + 1) * 32;
#pragma unroll
            for (int i = 0; i < 4; i++) {
                ra[i] = *(const float4*)(A + (size_t)(I + lrow[i]) * Nn + k0 + lkq[i]);
                rb[i] = *(const float4*)(A + (size_t)(J + lrow[i]) * Nn + k0 + lkq[i]);
            }
        }
        // compute on current buffer (LDG latency hides behind this)
#pragma unroll
        for (int kk = 0; kk < 32; kk += 8) {
            uint32_t af[2][4];
#pragma unroll
            for (int tm = 0; tm < 2; tm++) {
                int r = warp_m * 32 + tm * 16 + lr;
                int sw = (lr << 2);
                int c1 = (kk + lk + sw) & 31;
                int c2 = (kk + lk + 4 + sw) & 31;
                af[tm][0] = As[cur][r][c1];
                af[tm][1] = As[cur][r + 8][c1];
                af[tm][2] = As[cur][r][c2];
                af[tm][3] = As[cur][r + 8][c2];
            }
            uint32_t bf[8][2];
#pragma unroll
            for (int tn = 0; tn < 8; tn++) {
                int c = warp_n * 64 + tn * 8 + lr;
                int sw = (lr << 2);
                bf[tn][0] = Bs[cur][c][(kk + lk + sw) & 31];
                bf[tn][1] = Bs[cur][c][(kk + lk + 4 + sw) & 31];
            }
#pragma unroll
            for (int tm = 0; tm < 2; tm++)
#pragma unroll
                for (int tn = 0; tn < 8; tn++)
                    mma_tf32(acc[tm][tn], af[tm], bf[tn]);
        }
        if (hasNext) {
            int nxt = cur ^ 1;
#pragma unroll
            for (int i = 0; i < 4; i++) {
                As[nxt][lrow[i]][lpc[i] + 0] = f2tf32(ra[i].x); As[nxt][lrow[i]][lpc[i] + 1] = f2tf32(ra[i].y);
                As[nxt][lrow[i]][lpc[i] + 2] = f2tf32(ra[i].z); As[nxt][lrow[i]][lpc[i] + 3] = f2tf32(ra[i].w);
                Bs[nxt][lrow[i]][lpc[i] + 0] = f2tf32(rb[i].x); Bs[nxt][lrow[i]][lpc[i] + 1] = f2tf32(rb[i].y);
                Bs[nxt][lrow[i]][lpc[i] + 2] = f2tf32(rb[i].z); Bs[nxt][lrow[i]][lpc[i] + 3] = f2tf32(rb[i].w);
            }
        }
        __syncthreads();
    }

#pragma unroll
    for (int tm = 0; tm < 2; tm++) {
#pragma unroll
        for (int tn = 0; tn < 8; tn++) {
            int r = I + warp_m * 32 + tm * 16 + lr;
            int c = J + warp_n * 64 + tn * 8 + (lk << 1);
            C[(size_t)r * Nn + c] = acc[tm][tn][0];
            C[(size_t)r * Nn + c + 1] = acc[tm][tn][1];
            C[(size_t)(r + 8) * Nn + c] = acc[tm][tn][2];
            C[(size_t)(r + 8) * Nn + c + 1] = acc[tm][tn][3];
            if (bi != bj) {
                C[(size_t)c * Nn + r] = acc[tm][tn][0];
                C[(size_t)(c + 1) * Nn + r] = acc[tm][tn][1];
                C[(size_t)c * Nn + r + 8] = acc[tm][tn][2];
                C[(size_t)(c + 1) * Nn + r + 8] = acc[tm][tn][3];
            }
        }
    }
}

// ---------------- Y = A @ X  (X is [N,6]) ----------------
__global__ void matA_X_kernel(const float* __restrict__ A, const float* __restrict__ X,
                              float* __restrict__ Y) {
    __shared__ float sm[128 * Qq];
    int n = blockIdx.x;
    int tid = threadIdx.x;
    float acc[Qq] = {0, 0, 0, 0, 0, 0};
    const float* row = A + (size_t)n * Nn;
    for (int k = tid; k < Nn; k += 128) {
        float a = row[k];
#pragma unroll
        for (int q = 0; q < Qq; q++) acc[q] += a * X[k * Qq + q];
    }
#pragma unroll
    for (int q = 0; q < Qq; q++) sm[tid * Qq + q] = acc[q];
    __syncthreads();
    for (int o = 64; o; o >>= 1) {
        if (tid < o)
#pragma unroll
            for (int q = 0; q < Qq; q++) sm[tid * Qq + q] += sm[(tid + o) * Qq + q];
        __syncthreads();
    }
    if (tid < Qq) Y[n * Qq + tid] = sm[tid];
}

// ---------------- Z += A^T @ X (grid.y splits k, atomic accumulate; Z prezeroed) ----------------
__global__ void matAT_X_kernel(const float* __restrict__ A, const float* __restrict__ X,
                               float* __restrict__ Z) {
    __shared__ float Xs[512 * Qq];
    int n = blockIdx.x * 128 + threadIdx.x;
    int k0 = blockIdx.y * 512;
    for (int i = threadIdx.x; i < 512 * Qq; i += 128) Xs[i] = X[k0 * Qq + i];
    __syncthreads();
    float acc[Qq] = {0, 0, 0, 0, 0, 0};
    for (int kk = 0; kk < 512; kk++) {
        float a = A[(size_t)(k0 + kk) * Nn + n];
#pragma unroll
        for (int q = 0; q < Qq; q++) acc[q] += a * Xs[kk * Qq + q];
    }
#pragma unroll
    for (int q = 0; q < Qq; q++) atomicAdd(&Z[n * Qq + q], acc[q]);
}

// ---------------- shuffle-based block reduction helpers (256 threads, fp64) ----------------
__device__ __forceinline__ double shfl_red_d(double v) {
    for (int o = 16; o; o >>= 1) v += __shfl_down_sync(0xffffffffu, v, o);
    return v;
}

// ---------------- single-block MGS QR on [N,6], 256 thr, fp64, shuffle reductions ----------
__global__ void qr6f_kernel(float* __restrict__ Y) {
    __shared__ double sp[8 * 5];        // 8 warps x up to 5 values
    __shared__ double coefs[8];
    int tid = threadIdx.x;
    int lane = tid & 31, wrp = tid >> 5;
    for (int j = 0; j < Qq; j++) {
        double p = 0.0;
        for (int n = tid; n < Nn; n += 256) { double v = Y[n * Qq + j]; p += v * v; }
        p = shfl_red_d(p);
        if (lane == 0) sp[wrp] = p;
        __syncthreads();
        if (tid == 0) {
            double s = 0.0;
            for (int w = 0; w < 8; w++) s += sp[w];
            coefs[0] = (s > 0.0) ? (1.0 / sqrt(s)) : 0.0;
        }
        __syncthreads();
        float inv = (float)coefs[0];
        for (int n = tid; n < Nn; n += 256) Y[n * Qq + j] *= inv;
        __syncthreads();
        int nl = Qq - 1 - j;
        if (nl > 0) {
            double d[5] = {0, 0, 0, 0, 0};
            for (int n = tid; n < Nn; n += 256) {
                double yj = Y[n * Qq + j];
                for (int l = 0; l < nl; l++) d[l] += yj * (double)Y[n * Qq + j + 1 + l];
            }
            for (int l = 0; l < nl; l++) {
                d[l] = shfl_red_d(d[l]);
                if (lane == 0) sp[wrp * 5 + l] = d[l];
            }
            __syncthreads();
            if (tid < nl) {
                double s = 0.0;
                for (int w = 0; w < 8; w++) s += sp[w * 5 + tid];
                coefs[tid] = s;
            }
            __syncthreads();
            for (int n = tid; n < Nn; n += 256) {
                float yj = Y[n * Qq + j];
                for (int l = 0; l < nl; l++)
                    Y[n * Qq + j + 1 + l] -= (float)coefs[l] * yj;
            }
            __syncthreads();
        }
    }
}

// ---------------- one-sided Jacobi SVD on M=[N,6], 256 thr, shuffle reductions ----------
__global__ void osj_kernel(float* __restrict__ M, float* __restrict__ V) {
    __shared__ double sp[8 * 3];
    __shared__ double rot[3];
    __shared__ double nrm[Qq];
    __shared__ int nrot;
    int tid = threadIdx.x;
    int lane = tid & 31, wrp = tid >> 5;
    for (int sweep = 0; sweep < 10; sweep++) {
        if (tid == 0) nrot = 0;
        __syncthreads();
        for (int p = 0; p < Qq - 1; p++) {
            for (int q = p + 1; q < Qq; q++) {
                double da = 0.0, db = 0.0, dg = 0.0;
                for (int n = tid; n < Nn; n += 256) {
                    double mp = M[n * Qq + p], mq = M[n * Qq + q];
                    da += mp * mp; db += mq * mq; dg += mp * mq;
                }
                da = shfl_red_d(da);
                db = shfl_red_d(db);
                dg = shfl_red_d(dg);
                if (lane == 0) { sp[wrp * 3 + 0] = da; sp[wrp * 3 + 1] = db; sp[wrp * 3 + 2] = dg; }
                __syncthreads();
                if (tid == 0) {
                    double a = 0.0, b = 0.0, g = 0.0;
                    for (int w = 0; w < 8; w++) { a += sp[w * 3]; b += sp[w * 3 + 1]; g += sp[w * 3 + 2]; }
                    double thr = 1e-15 * sqrt(fmax(a * b, 0.0));
                    if (fabs(g) > thr && fabs(g) > 0.0) {
                        double z = (b - a) / (2.0 * g);
                        double tt = ((z >= 0.0) ? 1.0 : -1.0) / (fabs(z) + sqrt(1.0 + z * z));
                        double c = 1.0 / sqrt(1.0 + tt * tt);
                        rot[0] = c; rot[1] = tt * c; rot[2] = 1.0;
                        nrot++;
                    } else rot[2] = 0.0;
                }
                __syncthreads();
                if (rot[2] != 0.0) {
                    float c = (float)rot[0], s = (float)rot[1];
                    for (int n = tid; n < Nn; n += 256) {
                        float mp = M[n * Qq + p], mq = M[n * Qq + q];
                        M[n * Qq + p] = c * mp - s * mq;
                        M[n * Qq + q] = s * mp + c * mq;
                    }
                }
                __syncthreads();
            }
        }
        if (nrot == 0) break;
        __syncthreads();
    }
    for (int j = 0; j < Qq; j++) {
        double d = 0.0;
        for (int n = tid; n < Nn; n += 256) { double m = M[n * Qq + j]; d += m * m; }
        d = shfl_red_d(d);
        if (lane == 0) sp[wrp] = d;
        __syncthreads();
        if (tid == 0) {
            double s = 0.0;
            for (int w = 0; w < 8; w++) s += sp[w];
            nrm[j] = sqrt(s);
        }
        __syncthreads();
    }
    int idx[Qq] = {0, 1, 2, 3, 4, 5};
    for (int i = 0; i < Qq; i++)
        for (int j = i + 1; j < Qq; j++)
            if (nrm[idx[j]] > nrm[idx[i]]) { int t = idx[i]; idx[i] = idx[j]; idx[j] = t; }
    for (int k = 0; k < Qq; k++) {
        int j = idx[k];
        float inv = (nrm[j] > 0.0) ? (float)(1.0 / nrm[j]) : 0.f;
        for (int n = tid; n < Nn; n += 256) V[n * Qq + k] = M[n * Qq + j] * inv;
    }
}

// ---------------- matvec y = aa @ v (v strided) ----------------
__global__ void matvec_kernel(const float* __restrict__ aa, const float* __restrict__ v, int vs,
                              float* __restrict__ y) {
    __shared__ float sm[128];
    int n = blockIdx.x;
    const float* row = aa + (size_t)n * Nn;
    float p = 0.f;
    for (int k = threadIdx.x; k < Nn; k += 128) p += row[k] * v[k * vs];
    sm[threadIdx.x] = p; __syncthreads();
    for (int o = 64; o; o >>= 1) { if (threadIdx.x < o) sm[threadIdx.x] += sm[threadIdx.x + o]; __syncthreads(); }
    if (threadIdx.x == 0) y[n] = sm[0];
}

// ---------------- batched matvec: 3 strided columns of V ----------------
__global__ void matvec3s_kernel(const float* __restrict__ aa, const float* __restrict__ V,
                                float* __restrict__ y0, float* __restrict__ y1, float* __restrict__ y2) {
    __shared__ float sm[3][128];
    int n = blockIdx.x, tid = threadIdx.x;
    const float* row = aa + (size_t)n * Nn;
    float p0 = 0.f, p1 = 0.f, p2 = 0.f;
    for (int k = tid; k < Nn; k += 128) {
        float a = row[k];
        p0 += a * V[k * Qq + 0];
        p1 += a * V[k * Qq + 1];
        p2 += a * V[k * Qq + 2];
    }
    sm[0][tid] = p0; sm[1][tid] = p1; sm[2][tid] = p2;
    __syncthreads();
    for (int o = 64; o; o >>= 1) {
        if (tid < o) { sm[0][tid] += sm[0][tid + o]; sm[1][tid] += sm[1][tid + o]; sm[2][tid] += sm[2][tid + o]; }
        __syncthreads();
    }
    if (tid == 0) { y0[n] = sm[0][0]; y1[n] = sm[1][0]; y2[n] = sm[2][0]; }
}

// ---------------- batched matvec: 3 packed vectors ----------------
__global__ void matvec3p_kernel(const float* __restrict__ aa,
                                const float* __restrict__ v0, const float* __restrict__ v1,
                                const float* __restrict__ v2,
                                float* __restrict__ y0, float* __restrict__ y1, float* __restrict__ y2) {
    __shared__ float sm[3][128];
    int n = blockIdx.x, tid = threadIdx.x;
    const float* row = aa + (size_t)n * Nn;
    float p0 = 0.f, p1 = 0.f, p2 = 0.f;
    for (int k = tid; k < Nn; k += 128) {
        float a = row[k];
        p0 += a * v0[k];
        p1 += a * v1[k];
        p2 += a * v2[k];
    }
    sm[0][tid] = p0; sm[1][tid] = p1; sm[2][tid] = p2;
    __syncthreads();
    for (int o = 64; o; o >>= 1) {
        if (tid < o) { sm[0][tid] += sm[0][tid + o]; sm[1][tid] += sm[1][tid + o]; sm[2][tid] += sm[2][tid + o]; }
        __syncthreads();
    }
    if (tid == 0) { y0[n] = sm[0][0]; y1[n] = sm[1][0]; y2[n] = sm[2][0]; }
}

// ---------------- partial dots (no atomics, no prezero) ----------------
__global__ void dots_part_kernel(const float* __restrict__ w, const float* __restrict__ t,
                                 double* __restrict__ part) {
    __shared__ double s1[256], s2[256];
    int tid = threadIdx.x;
    int i = blockIdx.x * 256 + tid;
    double wv = w[i], tv = t[i];
    s1[tid] = wv * wv; s2[tid] = wv * tv;
    __syncthreads();
    for (int o = 128; o; o >>= 1) {
        if (tid < o) { s1[tid] += s1[tid + o]; s2[tid] += s2[tid + o]; }
        __syncthreads();
    }
    if (tid == 0) { part[blockIdx.x * 2] = s1[0]; part[blockIdx.x * 2 + 1] = s2[0]; }
}

__global__ void nuc_update2_kernel(const double* __restrict__ part, double* __restrict__ nuc,
                                   double* __restrict__ inv) {
    double ww = 0.0, wt = 0.0;
    for (int b = 0; b < 16; b++) { ww += part[b * 2]; wt += part[b * 2 + 1]; }
    ww = fmax(ww, 1e-300);
    *nuc += sqrt(fabs(wt / ww));
    *inv = 1.0 / ww;
}

// mode 0: aa *= (1 - vi vi^T) elementwise; mode 1: aa -= (aa vi) vi^T
__global__ void deflate4_kernel(float4* __restrict__ aa, const float* __restrict__ w,
                                const float* __restrict__ t, const double* __restrict__ inv_p,
                                int mode) {
    int idx = blockIdx.x * 256 + threadIdx.x;
    int i = idx >> 10;
    int j4 = (idx & 1023) << 2;
    float inv = (float)(*inv_p);
    float4 v = aa[idx];
    if (mode == 0) {
        float wi = w[i] * inv;
        v.x *= (1.f - wi * w[j4 + 0]);
        v.y *= (1.f - wi * w[j4 + 1]);
        v.z *= (1.f - wi * w[j4 + 2]);
        v.w *= (1.f - wi * w[j4 + 3]);
    } else {
        float ti = t[i] * inv;
        v.x -= ti * w[j4 + 0];
        v.y -= ti * w[j4 + 1];
        v.z -= ti * w[j4 + 2];
        v.w -= ti * w[j4 + 3];
    }
    aa[idx] = v;
}

__global__ void final_kernel(const float* __restrict__ red, const double* __restrict__ dred,
                             float* __restrict__ o_loss, float* __restrict__ o_calib) {
    float inv = 1.f / (float)Ee;
    float m1 = red[0] * inv, m2 = red[2] * inv;
    float c1 = red[1] * inv - m1 * m1;
    float c2 = red[3] * inv - m2 * m2;
    *o_loss = 0.01f * (c1 + c2) + 0.01f * (float)(dred[2] + dred[10]);
    *o_calib = red[5] / (float)Nn;
}

// ---------------- host orchestration ----------------
static void run_svd_nuc(const float* sd, const float* omega, float* aa, int mode,
                        float* Y, float* Z, float* Bt, float* V, float* W, float* T,
                        double* dredp, double* nuc, double* inv, cudaStream_t st) {
    matA_X_kernel<<<Nn, 128, 0, st>>>(sd, omega, Y);
    qr6f_kernel<<<1, 256, 0, st>>>(Y);
    for (int it = 0; it < 2; it++) {
        fill_kernel<<<(Nn * Qq + 255) / 256, 256, 0, st>>>(Z, 0.f, Nn * Qq);
        matAT_X_kernel<<<dim3(Nn / 128, 8), 128, 0, st>>>(sd, Y, Z);
        qr6f_kernel<<<1, 256, 0, st>>>(Z);
        matA_X_kernel<<<Nn, 128, 0, st>>>(sd, Z, Y);
        qr6f_kernel<<<1, 256, 0, st>>>(Y);
    }
    fill_kernel<<<(Nn * Qq + 255) / 256, 256, 0, st>>>(Bt, 0.f, Nn * Qq);
    matAT_X_kernel<<<dim3(Nn / 128, 8), 128, 0, st>>>(sd, Y, Bt);
    osj_kernel<<<1, 256, 0, st>>>(Bt, V);

    // nuc: k = 0..2 batched against undeflated aa
    matvec3s_kernel<<<Nn, 128, 0, st>>>(aa, V, W, W + Nn, W + 2 * Nn);
    matvec3p_kernel<<<Nn, 128, 0, st>>>(aa, W, W + Nn, W + 2 * Nn, T, T + Nn, T + 2 * Nn);
    for (int k = 0; k < 3; k++) {
        dots_part_kernel<<<16, 256, 0, st>>>(W + k * Nn, T + k * Nn, dredp);
        nuc_update2_kernel<<<1, 1, 0, st>>>(dredp, nuc, inv);
    }
    deflate4_kernel<<<(Nn * Nn / 4) / 256, 256, 0, st>>>((float4*)aa, W + 2 * Nn, T + 2 * Nn, inv, mode);
    for (int k = 3; k < Qq; k++) {
        matvec_kernel<<<Nn, 128, 0, st>>>(aa, V + k, Qq, W);
        matvec_kernel<<<Nn, 128, 0, st>>>(aa, W, 1, T);
        dots_part_kernel<<<16, 256, 0, st>>>(W, T, dredp);
        nuc_update2_kernel<<<1, 1, 0, st>>>(dredp, nuc, inv);
        if (k < 5)
            deflate4_kernel<<<(Nn * Nn / 4) / 256, 256, 0, st>>>((float4*)aa, W, T, inv, mode);
    }
}

extern "C" void kernel_launch(void* const* d_in, const int* in_sizes, int n_in,
                              void* d_out, int out_size) {
    const float* x      = (const float*)d_in[0];
    const int*   ei     = (const int*)d_in[1];
    const float* gcn1_w = (const float*)d_in[2];
    const float* gcn1_b = (const float*)d_in[3];
    const float* gcn2_w = (const float*)d_in[4];
    const float* gcn2_b = (const float*)d_in[5];
    const float* p1w1   = (const float*)d_in[6];
    const float* p1b1   = (const float*)d_in[7];
    const float* p1w2   = (const float*)d_in[8];
    const float* p1b2   = (const float*)d_in[9];
    const float* p2w1   = (const float*)d_in[10];
    const float* p2b1   = (const float*)d_in[11];
    const float* p2w2   = (const float*)d_in[12];
    const float* p2b2   = (const float*)d_in[13];
    const float* om1    = (const float*)d_in[14];
    const float* om2    = (const float*)d_in[15];

    float* out     = (float*)d_out;
    float* o_log   = out;                       // N*C
    float* o_sm    = out + Nn * Cc;             // N*C
    float* o_loss  = out + 2 * Nn * Cc;         // 1
    float* o_s1    = o_loss + 1;                // E
    float* o_s2    = o_s1 + Ee;                 // E
    float* o_calib = o_s2 + Ee;                 // 1

    float *s1d, *s2d, *aa1, *aa2, *h1, *x1, *hc, *xout, *deg, *Y, *Z, *Bt, *V, *wv, *tv, *red, *sg1, *sg2;
    double *dred, *dredp;
    cudaGetSymbolAddress((void**)&s1d, g_s1d);
    cudaGetSymbolAddress((void**)&s2d, g_s2d);
    cudaGetSymbolAddress((void**)&aa1, g_aa1);
    cudaGetSymbolAddress((void**)&aa2, g_aa2);
    cudaGetSymbolAddress((void**)&h1, g_h1);
    cudaGetSymbolAddress((void**)&x1, g_x1);
    cudaGetSymbolAddress((void**)&hc, g_hc);
    cudaGetSymbolAddress((void**)&xout, g_xout);
    cudaGetSymbolAddress((void**)&deg, g_deg);
    cudaGetSymbolAddress((void**)&Y, g_Y);
    cudaGetSymbolAddress((void**)&Z, g_Z);
    cudaGetSymbolAddress((void**)&Bt, g_Bt);
    cudaGetSymbolAddress((void**)&V, g_V);
    cudaGetSymbolAddress((void**)&wv, g_w);
    cudaGetSymbolAddress((void**)&tv, g_t);
    cudaGetSymbolAddress((void**)&red, g_red);
    cudaGetSymbolAddress((void**)&sg1, g_sg1);
    cudaGetSymbolAddress((void**)&sg2, g_sg2);
    cudaGetSymbolAddress((void**)&dred, g_dred);
    cudaGetSymbolAddress((void**)&dredp, g_dredp);

    static cudaStream_t sA = 0, sB = 0;
    static cudaEvent_t evS, evG1, evG2, evA, evB;
    if (!sA) {
        cudaStreamCreateWithFlags(&sA, cudaStreamNonBlocking);
        cudaStreamCreateWithFlags(&sB, cudaStreamNonBlocking);
        cudaEventCreateWithFlags(&evS, cudaEventDisableTiming);
        cudaEventCreateWithFlags(&evG1, cudaEventDisableTiming);
        cudaEventCreateWithFlags(&evG2, cudaEventDisableTiming);
        cudaEventCreateWithFlags(&evA, cudaEventDisableTiming);
        cudaEventCreateWithFlags(&evB, cudaEventDisableTiming);
    }

    zero_red_kernel<<<1, 32>>>(red, dred);

    // fork side streams; big adjacency fills overlap the gate phase
    cudaEventRecord(evS, 0);
    cudaStreamWaitEvent(sA, evS, 0);
    cudaStreamWaitEvent(sB, evS, 0);
    fill4_kernel<<<(Nn * Nn / 4) / 256, 256, 0, sA>>>((float4*)s1d, 1e-6f, Nn * Nn / 4);
    fill4_kernel<<<(Nn * Nn / 4) / 256, 256, 0, sB>>>((float4*)s2d, 1e-6f, Nn * Nn / 4);

    // gate 1 (internal buffer)
    gate1_kernel<<<Ee / 16, 256>>>(x, ei, p1w1, p1b1, p1w2, p1b2, sg1);
    cudaEventRecord(evG1, 0);

    // GCN conv 1
    xw_kernel<FIN, Hh><<<(Nn * Hh + 255) / 256, 256>>>(x, gcn1_w, h1);
    fill_kernel<<<(Nn + 255) / 256, 256>>>(deg, 1.0f, Nn);
    deg_acc_kernel<<<Ee / 256, 256>>>(ei, sg1, deg);
    deg_rsqrt_kernel<<<(Nn + 255) / 256, 256>>>(deg);
    init_out_kernel<Hh><<<(Nn * Hh + 255) / 256, 256>>>(h1, deg, x1);
    scatter_kernel<Hh><<<(Ee * Hh + 255) / 256, 256>>>(ei, sg1, deg, h1, x1);
    bias_act_kernel<Hh, 1><<<(Nn * Hh + 255) / 256, 256>>>(x1, gcn1_b);

    // gate 2 (internal buffer)
    gate2_kernel<<<Ee / 8, 256>>>(x1, ei, p2w1, p2b1, p2w2, p2b2, sg2);
    cudaEventRecord(evG2, 0);

    int ntile = Nn / 128;
    int ngrid = ntile * (ntile + 1) / 2;

    // branch A: adjacency 1 -> syrk -> svd+nuc (depends only on sg1)
    cudaStreamWaitEvent(sA, evG1, 0);
    scatter_dense_kernel<<<Ee / 256, 256, 0, sA>>>(ei, sg1, s1d);
    syrk_tc_kernel<<<ngrid, 256, 0, sA>>>(s1d, aa1);
    run_svd_nuc(s1d, om1, aa1, 0, Y, Z, Bt, V, wv, tv,
                dredp, &dred[2], &dred[3], sA);

    // branch B: adjacency 2 -> syrk -> svd+nuc (depends only on sg2)
    cudaStreamWaitEvent(sB, evG2, 0);
    scatter_dense_kernel<<<Ee / 256, 256, 0, sB>>>(ei, sg2, s2d);
    syrk_tc_kernel<<<ngrid, 256, 0, sB>>>(s2d, aa2);
    run_svd_nuc(s2d, om2, aa2, 1, Y + Nn * Qq, Z + Nn * Qq, Bt + Nn * Qq, V + Nn * Qq,
                wv + 3 * Nn, tv + 3 * Nn, dredp + 32, &dred[10], &dred[11], sB);

    // default stream: GCN conv 2 + softmax/consist (overlaps branches)
    xw_kernel<Hh, Cc><<<(Nn * Cc + 255) / 256, 256>>>(x1, gcn2_w, hc);
    fill_kernel<<<(Nn + 255) / 256, 256>>>(deg, 1.0f, Nn);
    deg_acc_kernel<<<Ee / 256, 256>>>(ei, sg2, deg);
    deg_rsqrt_kernel<<<(Nn + 255) / 256, 256>>>(deg);
    init_out_kernel<Cc><<<(Nn * Cc + 255) / 256, 256>>>(hc, deg, xout);
    scatter_kernel<Cc><<<(Ee * Cc + 255) / 256, 256>>>(ei, sg2, deg, hc, xout);
    bias_act_kernel<Cc, 0><<<(Nn * Cc + 255) / 256, 256>>>(xout, gcn2_b);
    softmax_kernel<<<Nn / 128, 128>>>(xout, o_log, o_sm, red);
    consist_kernel<<<Ee / 256, 256>>>(sg1, sg2, red);
    copy2_kernel<<<Ee / 256, 256>>>(sg1, o_s1, sg2, o_s2);

    // join
    cudaEventRecord(evA, sA);
    cudaEventRecord(evB, sB);
    cudaStreamWaitEvent(0, evA, 0);
    cudaStreamWaitEvent(0, evB, 0);

    final_kernel<<<1, 1>>>(red, dred, o_loss, o_calib);
}